// round 2
// baseline (speedup 1.0000x reference)
#include <cuda_runtime.h>
#include <cstdint>

#define NN   4096
#define BB   16
#define NB   256      // nodes per batch
#define ND   9        // NUM_DEG
#define FF   128
#define MCH  1152     // 9*128
#define NFREQ 64

// ---------------- scratch (static device memory; no allocations) ------------
__device__ float g_q[NN * MCH];
__device__ float g_k[NN * MCH];
__device__ float g_v[NN * MCH];
__device__ float g_cos[NN * 3 * NFREQ];
__device__ float g_sin[NN * 3 * NFREQ];
__device__ float g_Spart[9u * BB * NB * NB];   // 9 partial slabs
__device__ float g_S[BB * NB * NB];

// ---------------- packed f32x2 helpers --------------------------------------
__device__ __forceinline__ unsigned long long splat2(float x) {
    unsigned long long r;
    asm("mov.b64 %0, {%1, %1};" : "=l"(r) : "f"(x));
    return r;
}
__device__ __forceinline__ void fma2(unsigned long long& d,
                                     unsigned long long a,
                                     unsigned long long b) {
    asm("fma.rn.f32x2 %0, %1, %2, %0;" : "+l"(d) : "l"(a), "l"(b));
}
__device__ __forceinline__ float2 unpack2(unsigned long long v) {
    float2 r;
    asm("mov.b64 {%0, %1}, %2;" : "=f"(r.x), "=f"(r.y) : "l"(v));
    return r;
}

// ---------------- kernel: cos/sin tables ------------------------------------
__global__ void k_cs(const float* __restrict__ pos) {
    int idx = blockIdx.x * 256 + threadIdx.x;
    if (idx >= NN * 3 * NFREQ) return;
    int c = idx & 63;
    int a = (idx >> 6) % 3;
    int n = idx / 192;
    float theta = (8.0f / (63.0f * 10.0f)) * (float)c;  // linspace(0,8,64)/10
    float ph = pos[n * 3 + a] * theta;
    float s, co;
    sincosf(ph, &s, &co);
    g_cos[idx] = co;
    g_sin[idx] = s;
}

// ---------------- kernel: q/k/v projections ----------------------------------
// z = p*3 + l  (p: 0=q 1=k 2=v; l: degree group). Rows = (node, m) pairs of
// that group; per-CTA 128x128x128 GEMM, fp32, f32x2 inner.
__global__ void __launch_bounds__(256, 2)
k_proj(const float* __restrict__ X,
       const float* __restrict__ Wq, const float* __restrict__ bq,
       const float* __restrict__ Wk, const float* __restrict__ bk,
       const float* __restrict__ Wv, const float* __restrict__ bv) {
    extern __shared__ float sm[];
    float* As = sm;             // [32][132]  ([f][row])
    float* Ws = sm + 32 * 132;  // [32][128]  ([f][t])

    int z = blockIdx.z;
    int p = z / 3, l = z % 3;
    const int cnt = (l == 0) ? 1 : (l == 1 ? 3 : 5);
    const int m0  = (l == 0) ? 0 : (l == 1 ? 1 : 4);
    int ntiles = (NN * cnt) >> 7;
    if ((int)blockIdx.x >= ntiles) return;

    const float* W    = (p == 0 ? Wq : (p == 1 ? Wk : Wv)) + l * FF * FF;
    const float* bias = (p == 0 ? bq : (p == 1 ? bk : bv));
    float* dst = (p == 0 ? g_q : (p == 1 ? g_k : g_v));

    int row0 = blockIdx.x * 128;
    int tid = threadIdx.x;
    int tx = tid & 15, ty = tid >> 4;
    int scg = tid & 7, sr0 = tid >> 3;
    int wt = tid & 31, wf = tid >> 5;

    const float* arow[4];
#pragma unroll
    for (int i = 0; i < 4; i++) {
        int rg = row0 + sr0 + i * 32;
        int node = rg / cnt, mi = rg - node * cnt;
        arow[i] = X + ((size_t)node * ND + (m0 + mi)) * FF;
    }
    int orow[8];
#pragma unroll
    for (int i = 0; i < 8; i++) {
        int rg = row0 + ty * 8 + i;
        int node = rg / cnt, mi = rg - node * cnt;
        orow[i] = node * MCH + (m0 + mi) * FF;
    }

    unsigned long long acc[8][4];
#pragma unroll
    for (int i = 0; i < 8; i++)
#pragma unroll
        for (int j = 0; j < 4; j++) acc[i][j] = 0ull;

    for (int kc = 0; kc < 4; kc++) {
        int f0 = kc * 32;
        __syncthreads();
#pragma unroll
        for (int i = 0; i < 4; i++) {
            float4 v = *(const float4*)(arow[i] + f0 + scg * 4);
            int r = sr0 + i * 32;
            int cl = scg * 4;
            As[(cl + 0) * 132 + r] = v.x;
            As[(cl + 1) * 132 + r] = v.y;
            As[(cl + 2) * 132 + r] = v.z;
            As[(cl + 3) * 132 + r] = v.w;
        }
#pragma unroll
        for (int i = 0; i < 4; i++) {
            int f = wf + i * 8;
            *(float4*)(Ws + f * 128 + wt * 4) =
                *(const float4*)(W + (size_t)(f0 + f) * 128 + wt * 4);
        }
        __syncthreads();
#pragma unroll 8
        for (int kk = 0; kk < 32; kk++) {
            float4 a0 = *(const float4*)(As + kk * 132 + ty * 8);
            float4 a1 = *(const float4*)(As + kk * 132 + ty * 8 + 4);
            ulonglong2 b0 = *(const ulonglong2*)(Ws + kk * 128 + tx * 8);
            ulonglong2 b1 = *(const ulonglong2*)(Ws + kk * 128 + tx * 8 + 4);
            unsigned long long bb0 = b0.x, bb1 = b0.y, bb2 = b1.x, bb3 = b1.y;
            unsigned long long a;
            a = splat2(a0.x); fma2(acc[0][0],a,bb0); fma2(acc[0][1],a,bb1); fma2(acc[0][2],a,bb2); fma2(acc[0][3],a,bb3);
            a = splat2(a0.y); fma2(acc[1][0],a,bb0); fma2(acc[1][1],a,bb1); fma2(acc[1][2],a,bb2); fma2(acc[1][3],a,bb3);
            a = splat2(a0.z); fma2(acc[2][0],a,bb0); fma2(acc[2][1],a,bb1); fma2(acc[2][2],a,bb2); fma2(acc[2][3],a,bb3);
            a = splat2(a0.w); fma2(acc[3][0],a,bb0); fma2(acc[3][1],a,bb1); fma2(acc[3][2],a,bb2); fma2(acc[3][3],a,bb3);
            a = splat2(a1.x); fma2(acc[4][0],a,bb0); fma2(acc[4][1],a,bb1); fma2(acc[4][2],a,bb2); fma2(acc[4][3],a,bb3);
            a = splat2(a1.y); fma2(acc[5][0],a,bb0); fma2(acc[5][1],a,bb1); fma2(acc[5][2],a,bb2); fma2(acc[5][3],a,bb3);
            a = splat2(a1.z); fma2(acc[6][0],a,bb0); fma2(acc[6][1],a,bb1); fma2(acc[6][2],a,bb2); fma2(acc[6][3],a,bb3);
            a = splat2(a1.w); fma2(acc[7][0],a,bb0); fma2(acc[7][1],a,bb1); fma2(acc[7][2],a,bb2); fma2(acc[7][3],a,bb3);
        }
    }

    float bcol[8];
#pragma unroll
    for (int j = 0; j < 8; j++) bcol[j] = (l == 0) ? bias[tx * 8 + j] : 0.0f;
#pragma unroll
    for (int i = 0; i < 8; i++) {
#pragma unroll
        for (int j = 0; j < 4; j++) {
            float2 v = unpack2(acc[i][j]);
            v.x += bcol[j * 2];
            v.y += bcol[j * 2 + 1];
            *(float2*)(dst + (size_t)orow[i] + tx * 8 + j * 2) = v;
        }
    }
}

// ---------------- kernel: score partials -------------------------------------
// grid: x=ti(2), y=tj(2), z = b*9 + (a*3 + mchunk). Each CTA: 128x128 tile of
// S_part over K = 384 channels x {cos,sin}. RoPE fused at staging.
__global__ void __launch_bounds__(256, 2)
k_score() {
    extern __shared__ float sm[];
    float* As = sm;                  // [2][32][132]
    float* Bs = sm + 2 * 32 * 132;   // [2][32][132]

    int zz = blockIdx.z;
    int b = zz / 9, sp = zz - b * 9;
    int a = sp / 3, mc = sp - a * 3;
    int nb_i = b * NB + blockIdx.x * 128;
    int nb_j = b * NB + blockIdx.y * 128;
    int tid = threadIdx.x;
    int tx = tid & 15, ty = tid >> 4;
    int scg = tid & 7, sr0 = tid >> 3;

    unsigned long long acc[8][4];
#pragma unroll
    for (int i = 0; i < 8; i++)
#pragma unroll
        for (int j = 0; j < 4; j++) acc[i][j] = 0ull;

    int chbase = mc * 384;
    for (int c = 0; c < 12; c++) {
        int ch0 = chbase + c * 32;
        __syncthreads();
#pragma unroll
        for (int i = 0; i < 4; i++) {
            int r = sr0 + i * 32;
            int ch = ch0 + scg * 4;
            int f = (ch & 127) >> 1;
            int ni = nb_i + r, nj = nb_j + r;
            const float* cbi = g_cos + ni * 192 + a * 64;
            const float* sbi = g_sin + ni * 192 + a * 64;
            const float* cbj = g_cos + nj * 192 + a * 64;
            const float* sbj = g_sin + nj * 192 + a * 64;
            float c0 = cbi[f], c1 = cbi[f + 1], s0 = sbi[f], s1 = sbi[f + 1];
            float d0 = cbj[f], d1 = cbj[f + 1], t0 = sbj[f], t1 = sbj[f + 1];
            float4 qv = *(const float4*)(g_q + (size_t)ni * MCH + ch);
            float4 kw = *(const float4*)(g_k + (size_t)nj * MCH + ch);
            int cl = scg * 4;
            float* Ac = As + cl * 132 + r;
            float* An = As + (32 + cl) * 132 + r;
            Ac[0 * 132] = qv.x * c0; Ac[1 * 132] = qv.y * c0;
            Ac[2 * 132] = qv.z * c1; Ac[3 * 132] = qv.w * c1;
            An[0 * 132] = qv.x * s0; An[1 * 132] = qv.y * s0;
            An[2 * 132] = qv.z * s1; An[3 * 132] = qv.w * s1;
            float* Bc = Bs + cl * 132 + r;
            float* Bn = Bs + (32 + cl) * 132 + r;
            Bc[0 * 132] = kw.x * d0; Bc[1 * 132] = kw.y * d0;
            Bc[2 * 132] = kw.z * d1; Bc[3 * 132] = kw.w * d1;
            Bn[0 * 132] = kw.x * t0; Bn[1 * 132] = kw.y * t0;
            Bn[2 * 132] = kw.z * t1; Bn[3 * 132] = kw.w * t1;
        }
        __syncthreads();
#pragma unroll
        for (int s = 0; s < 2; s++) {
            const float* Ab = As + s * 32 * 132;
            const float* Bb = Bs + s * 32 * 132;
#pragma unroll 8
            for (int kk = 0; kk < 32; kk++) {
                float4 a0 = *(const float4*)(Ab + kk * 132 + ty * 8);
                float4 a1 = *(const float4*)(Ab + kk * 132 + ty * 8 + 4);
                ulonglong2 b0 = *(const ulonglong2*)(Bb + kk * 132 + tx * 8);
                ulonglong2 b1 = *(const ulonglong2*)(Bb + kk * 132 + tx * 8 + 4);
                unsigned long long bb0 = b0.x, bb1 = b0.y, bb2 = b1.x, bb3 = b1.y;
                unsigned long long av;
                av = splat2(a0.x); fma2(acc[0][0],av,bb0); fma2(acc[0][1],av,bb1); fma2(acc[0][2],av,bb2); fma2(acc[0][3],av,bb3);
                av = splat2(a0.y); fma2(acc[1][0],av,bb0); fma2(acc[1][1],av,bb1); fma2(acc[1][2],av,bb2); fma2(acc[1][3],av,bb3);
                av = splat2(a0.z); fma2(acc[2][0],av,bb0); fma2(acc[2][1],av,bb1); fma2(acc[2][2],av,bb2); fma2(acc[2][3],av,bb3);
                av = splat2(a0.w); fma2(acc[3][0],av,bb0); fma2(acc[3][1],av,bb1); fma2(acc[3][2],av,bb2); fma2(acc[3][3],av,bb3);
                av = splat2(a1.x); fma2(acc[4][0],av,bb0); fma2(acc[4][1],av,bb1); fma2(acc[4][2],av,bb2); fma2(acc[4][3],av,bb3);
                av = splat2(a1.y); fma2(acc[5][0],av,bb0); fma2(acc[5][1],av,bb1); fma2(acc[5][2],av,bb2); fma2(acc[5][3],av,bb3);
                av = splat2(a1.z); fma2(acc[6][0],av,bb0); fma2(acc[6][1],av,bb1); fma2(acc[6][2],av,bb2); fma2(acc[6][3],av,bb3);
                av = splat2(a1.w); fma2(acc[7][0],av,bb0); fma2(acc[7][1],av,bb1); fma2(acc[7][2],av,bb2); fma2(acc[7][3],av,bb3);
            }
        }
    }

    size_t base = ((size_t)sp * BB + b) * (NB * NB);
    int i0 = blockIdx.x * 128 + ty * 8;
    int j0 = blockIdx.y * 128 + tx * 8;
#pragma unroll
    for (int i = 0; i < 8; i++) {
        unsigned long long* dp =
            (unsigned long long*)(g_Spart + base + (size_t)(i0 + i) * NB + j0);
        dp[0] = acc[i][0]; dp[1] = acc[i][1]; dp[2] = acc[i][2]; dp[3] = acc[i][3];
    }
}

// ---------------- kernel: slab reduce -----------------------------------------
__global__ void k_reduceS() {
    int i = blockIdx.x * 256 + threadIdx.x;
    const int SZ = BB * NB * NB;
    if (i >= SZ) return;
    float s = 0.0f;
#pragma unroll
    for (int sl = 0; sl < 9; sl++) s += g_Spart[(size_t)sl * SZ + i];
    g_S[i] = s * (1.0f / 3.0f);   // = 2 * grid_w (pairing factor * 1/6)
}

// ---------------- kernel: out = Sbar @ V (+mask) ------------------------------
__global__ void __launch_bounds__(256)
k_out(const int* __restrict__ bseg, const int* __restrict__ gmask,
      float* __restrict__ out) {
    extern __shared__ float sm[];
    float* Ss = sm;            // [64][68]   ([kk][row])
    float* Vs = sm + 64 * 68;  // [64][132]  ([kk][col])

    int b = blockIdx.z;
    int r0 = blockIdx.x * 64;
    int d0 = blockIdx.y * 128;
    int tid = threadIdx.x;
    int tx = tid & 15, ty = tid >> 4;

    unsigned long long acc[4][4];
#pragma unroll
    for (int i = 0; i < 4; i++)
#pragma unroll
        for (int j = 0; j < 4; j++) acc[i][j] = 0ull;

    int jg = tid & 15, rw = tid >> 4;
    int cg = tid & 31, k0 = tid >> 5;

    for (int jc = 0; jc < 4; jc++) {
        int j0 = jc * 64;
        __syncthreads();
#pragma unroll
        for (int i = 0; i < 4; i++) {
            int row = rw + i * 16;
            float4 v = *(const float4*)(g_S + ((size_t)b * NB + r0 + row) * NB + j0 + jg * 4);
            Ss[(jg * 4 + 0) * 68 + row] = v.x;
            Ss[(jg * 4 + 1) * 68 + row] = v.y;
            Ss[(jg * 4 + 2) * 68 + row] = v.z;
            Ss[(jg * 4 + 3) * 68 + row] = v.w;
        }
#pragma unroll
        for (int i = 0; i < 8; i++) {
            int kk = k0 + i * 8;
            *(float4*)(Vs + kk * 132 + cg * 4) =
                *(const float4*)(g_v + ((size_t)b * NB + j0 + kk) * MCH + d0 + cg * 4);
        }
        __syncthreads();
#pragma unroll 8
        for (int kk = 0; kk < 64; kk++) {
            float4 s4 = *(const float4*)(Ss + kk * 68 + ty * 4);
            ulonglong2 v0 = *(const ulonglong2*)(Vs + kk * 132 + tx * 8);
            ulonglong2 v1 = *(const ulonglong2*)(Vs + kk * 132 + tx * 8 + 4);
            unsigned long long bb0 = v0.x, bb1 = v0.y, bb2 = v1.x, bb3 = v1.y;
            unsigned long long av;
            av = splat2(s4.x); fma2(acc[0][0],av,bb0); fma2(acc[0][1],av,bb1); fma2(acc[0][2],av,bb2); fma2(acc[0][3],av,bb3);
            av = splat2(s4.y); fma2(acc[1][0],av,bb0); fma2(acc[1][1],av,bb1); fma2(acc[1][2],av,bb2); fma2(acc[1][3],av,bb3);
            av = splat2(s4.z); fma2(acc[2][0],av,bb0); fma2(acc[2][1],av,bb1); fma2(acc[2][2],av,bb2); fma2(acc[2][3],av,bb3);
            av = splat2(s4.w); fma2(acc[3][0],av,bb0); fma2(acc[3][1],av,bb1); fma2(acc[3][2],av,bb2); fma2(acc[3][3],av,bb3);
        }
    }

#pragma unroll
    for (int r = 0; r < 4; r++) {
        int node = b * NB + r0 + ty * 4 + r;
        bool mk = gmask[bseg[node]] != 0;
#pragma unroll
        for (int j = 0; j < 4; j++) {
            unsigned long long v = mk ? acc[r][j] : 0ull;
            *(unsigned long long*)(out + (size_t)node * MCH + d0 + tx * 8 + j * 2) = v;
        }
    }
}

// ---------------- launcher ----------------------------------------------------
extern "C" void kernel_launch(void* const* d_in, const int* in_sizes, int n_in,
                              void* d_out, int out_size) {
    const float* X   = (const float*)d_in[0];
    const float* pos = (const float*)d_in[1];
    const int* bseg  = (const int*)d_in[2];
    const int* gmask = (const int*)d_in[3];   // bool -> int32 in harness
    const float* Wq = (const float*)d_in[4];
    const float* bq = (const float*)d_in[5];
    const float* Wk = (const float*)d_in[6];
    const float* bk = (const float*)d_in[7];
    const float* Wv = (const float*)d_in[8];
    const float* bv = (const float*)d_in[9];
    float* out = (float*)d_out;

    cudaFuncSetAttribute(k_proj,  cudaFuncAttributeMaxDynamicSharedMemorySize, 33280);
    cudaFuncSetAttribute(k_score, cudaFuncAttributeMaxDynamicSharedMemorySize, 67584);
    cudaFuncSetAttribute(k_out,   cudaFuncAttributeMaxDynamicSharedMemorySize, 51200);

    k_cs<<<(NN * 3 * NFREQ + 255) / 256, 256>>>(pos);
    k_proj<<<dim3(160, 1, 9), 256, 33280>>>(X, Wq, bq, Wk, bk, Wv, bv);
    k_score<<<dim3(2, 2, BB * 9), 256, 67584>>>();
    k_reduceS<<<(BB * NB * NB) / 256, 256>>>();
    k_out<<<dim3(4, 9, BB), 256, 51200>>>(bseg, gmask, out);
}

// round 3
// speedup vs baseline: 1.5653x; 1.5653x over previous
#include <cuda_runtime.h>
#include <cuda_bf16.h>
#include <cstdint>

#define NN   4096
#define BB   16
#define NB   256      // nodes per batch
#define ND   9        // NUM_DEG
#define FF   128
#define MCH  1152     // 9*128
#define NFREQ 64

// ---------------- scratch (static device memory; no allocations) ------------
__device__ float g_q[NN * MCH];
__device__ float g_k[NN * MCH];
__device__ float g_v[NN * MCH];
__device__ float g_cos[NN * 3 * NFREQ];
__device__ float g_sin[NN * 3 * NFREQ];
__device__ float g_Spart[9u * BB * NB * NB];   // 9 partial slabs
__device__ float g_S[BB * NB * NB];

// ---------------- packed f32x2 helpers (k_proj / k_out) ---------------------
__device__ __forceinline__ unsigned long long splat2(float x) {
    unsigned long long r;
    asm("mov.b64 %0, {%1, %1};" : "=l"(r) : "f"(x));
    return r;
}
__device__ __forceinline__ void fma2(unsigned long long& d,
                                     unsigned long long a,
                                     unsigned long long b) {
    asm("fma.rn.f32x2 %0, %1, %2, %0;" : "+l"(d) : "l"(a), "l"(b));
}
__device__ __forceinline__ float2 unpack2(unsigned long long v) {
    float2 r;
    asm("mov.b64 {%0, %1}, %2;" : "=f"(r.x), "=f"(r.y) : "l"(v));
    return r;
}

// ---------------- mma helpers -------------------------------------------------
__device__ __forceinline__ uint32_t cvsm(const void* p) {
    return (uint32_t)__cvta_generic_to_shared(p);
}
__device__ __forceinline__ void ldsm4(uint32_t* r, uint32_t addr) {
    asm volatile("ldmatrix.sync.aligned.m8n8.x4.shared.b16 {%0,%1,%2,%3}, [%4];"
                 : "=r"(r[0]), "=r"(r[1]), "=r"(r[2]), "=r"(r[3])
                 : "r"(addr));
}
__device__ __forceinline__ void mma16816(float* d, const uint32_t* a,
                                         uint32_t b0, uint32_t b1) {
    asm volatile(
        "mma.sync.aligned.m16n8k16.row.col.f32.bf16.bf16.f32 "
        "{%0,%1,%2,%3}, {%4,%5,%6,%7}, {%8,%9}, {%0,%1,%2,%3};"
        : "+f"(d[0]), "+f"(d[1]), "+f"(d[2]), "+f"(d[3])
        : "r"(a[0]), "r"(a[1]), "r"(a[2]), "r"(a[3]), "r"(b0), "r"(b1));
}

// ---------------- kernel: cos/sin tables ------------------------------------
__global__ void k_cs(const float* __restrict__ pos) {
    int idx = blockIdx.x * 256 + threadIdx.x;
    if (idx >= NN * 3 * NFREQ) return;
    int c = idx & 63;
    int a = (idx >> 6) % 3;
    int n = idx / 192;
    float theta = (8.0f / (63.0f * 10.0f)) * (float)c;  // linspace(0,8,64)/10
    float ph = pos[n * 3 + a] * theta;
    float s, co;
    sincosf(ph, &s, &co);
    g_cos[idx] = co;
    g_sin[idx] = s;
}

// ---------------- kernel: q/k/v projections (FFMA2, unchanged) ---------------
__global__ void __launch_bounds__(256, 2)
k_proj(const float* __restrict__ X,
       const float* __restrict__ Wq, const float* __restrict__ bq,
       const float* __restrict__ Wk, const float* __restrict__ bk,
       const float* __restrict__ Wv, const float* __restrict__ bv) {
    extern __shared__ float sm[];
    float* As = sm;             // [32][132]
    float* Ws = sm + 32 * 132;  // [32][128]

    int z = blockIdx.z;
    int p = z / 3, l = z % 3;
    const int cnt = (l == 0) ? 1 : (l == 1 ? 3 : 5);
    const int m0  = (l == 0) ? 0 : (l == 1 ? 1 : 4);
    int ntiles = (NN * cnt) >> 7;
    if ((int)blockIdx.x >= ntiles) return;

    const float* W    = (p == 0 ? Wq : (p == 1 ? Wk : Wv)) + l * FF * FF;
    const float* bias = (p == 0 ? bq : (p == 1 ? bk : bv));
    float* dst = (p == 0 ? g_q : (p == 1 ? g_k : g_v));

    int row0 = blockIdx.x * 128;
    int tid = threadIdx.x;
    int tx = tid & 15, ty = tid >> 4;
    int scg = tid & 7, sr0 = tid >> 3;
    int wt = tid & 31, wf = tid >> 5;

    const float* arow[4];
#pragma unroll
    for (int i = 0; i < 4; i++) {
        int rg = row0 + sr0 + i * 32;
        int node = rg / cnt, mi = rg - node * cnt;
        arow[i] = X + ((size_t)node * ND + (m0 + mi)) * FF;
    }
    int orow[8];
#pragma unroll
    for (int i = 0; i < 8; i++) {
        int rg = row0 + ty * 8 + i;
        int node = rg / cnt, mi = rg - node * cnt;
        orow[i] = node * MCH + (m0 + mi) * FF;
    }

    unsigned long long acc[8][4];
#pragma unroll
    for (int i = 0; i < 8; i++)
#pragma unroll
        for (int j = 0; j < 4; j++) acc[i][j] = 0ull;

    for (int kc = 0; kc < 4; kc++) {
        int f0 = kc * 32;
        __syncthreads();
#pragma unroll
        for (int i = 0; i < 4; i++) {
            float4 v = *(const float4*)(arow[i] + f0 + scg * 4);
            int r = sr0 + i * 32;
            int cl = scg * 4;
            As[(cl + 0) * 132 + r] = v.x;
            As[(cl + 1) * 132 + r] = v.y;
            As[(cl + 2) * 132 + r] = v.z;
            As[(cl + 3) * 132 + r] = v.w;
        }
#pragma unroll
        for (int i = 0; i < 4; i++) {
            int f = wf + i * 8;
            *(float4*)(Ws + f * 128 + wt * 4) =
                *(const float4*)(W + (size_t)(f0 + f) * 128 + wt * 4);
        }
        __syncthreads();
#pragma unroll 8
        for (int kk = 0; kk < 32; kk++) {
            float4 a0 = *(const float4*)(As + kk * 132 + ty * 8);
            float4 a1 = *(const float4*)(As + kk * 132 + ty * 8 + 4);
            ulonglong2 b0 = *(const ulonglong2*)(Ws + kk * 128 + tx * 8);
            ulonglong2 b1 = *(const ulonglong2*)(Ws + kk * 128 + tx * 8 + 4);
            unsigned long long bb0 = b0.x, bb1 = b0.y, bb2 = b1.x, bb3 = b1.y;
            unsigned long long a;
            a = splat2(a0.x); fma2(acc[0][0],a,bb0); fma2(acc[0][1],a,bb1); fma2(acc[0][2],a,bb2); fma2(acc[0][3],a,bb3);
            a = splat2(a0.y); fma2(acc[1][0],a,bb0); fma2(acc[1][1],a,bb1); fma2(acc[1][2],a,bb2); fma2(acc[1][3],a,bb3);
            a = splat2(a0.z); fma2(acc[2][0],a,bb0); fma2(acc[2][1],a,bb1); fma2(acc[2][2],a,bb2); fma2(acc[2][3],a,bb3);
            a = splat2(a0.w); fma2(acc[3][0],a,bb0); fma2(acc[3][1],a,bb1); fma2(acc[3][2],a,bb2); fma2(acc[3][3],a,bb3);
            a = splat2(a1.x); fma2(acc[4][0],a,bb0); fma2(acc[4][1],a,bb1); fma2(acc[4][2],a,bb2); fma2(acc[4][3],a,bb3);
            a = splat2(a1.y); fma2(acc[5][0],a,bb0); fma2(acc[5][1],a,bb1); fma2(acc[5][2],a,bb2); fma2(acc[5][3],a,bb3);
            a = splat2(a1.z); fma2(acc[6][0],a,bb0); fma2(acc[6][1],a,bb1); fma2(acc[6][2],a,bb2); fma2(acc[6][3],a,bb3);
            a = splat2(a1.w); fma2(acc[7][0],a,bb0); fma2(acc[7][1],a,bb1); fma2(acc[7][2],a,bb2); fma2(acc[7][3],a,bb3);
        }
    }

    float bcol[8];
#pragma unroll
    for (int j = 0; j < 8; j++) bcol[j] = (l == 0) ? bias[tx * 8 + j] : 0.0f;
#pragma unroll
    for (int i = 0; i < 8; i++) {
#pragma unroll
        for (int j = 0; j < 4; j++) {
            float2 v = unpack2(acc[i][j]);
            v.x += bcol[j * 2];
            v.y += bcol[j * 2 + 1];
            *(float2*)(dst + (size_t)orow[i] + tx * 8 + j * 2) = v;
        }
    }
}

// ---------------- kernel: score partials via bf16 hi/lo mma.sync --------------
// grid: x=ti(2), y=tj(2), z = b*9 + (a*3 + mchunk). 128x128 tile, K=768
// (= 384 channels x {cos,sin}), RoPE scale + hi/lo split fused at staging.
// acc += Ah*Bh + Ah*Bl + Al*Bh   (fp32 accumulate; Al*Bl ~ 2^-18, dropped)
#define SPITCH 40           // bf16 elements per smem row (80 B, conflict-free)
#define SARR   (128 * SPITCH)

__global__ void __launch_bounds__(256, 2)
k_score() {
    extern __shared__ unsigned char smraw[];
    __nv_bfloat16* smb = (__nv_bfloat16*)smraw;
    // layout: [stage(2)][arr(4): Ah Al Bh Bl][128][SPITCH]

    int zz = blockIdx.z;
    int b = zz / 9, sp = zz - b * 9;
    int a = sp / 3, mc = sp - a * 3;
    int nb_i = b * NB + blockIdx.x * 128;
    int nb_j = b * NB + blockIdx.y * 128;
    int tid = threadIdx.x;
    int wid = tid >> 5, lane = tid & 31;
    int wm = wid & 3, wn = wid >> 2;        // warp tile (wm*32, wn*64)

    float acc[2][8][4];
#pragma unroll
    for (int mt = 0; mt < 2; mt++)
#pragma unroll
        for (int nt = 0; nt < 8; nt++)
#pragma unroll
            for (int e = 0; e < 4; e++) acc[mt][nt][e] = 0.0f;

    int kq = tid & 7, rr = tid >> 3;
    int chbase = mc * 384;

    // ldmatrix lane address components
    int at_r = (lane & 7) + ((lane >> 3) & 1) * 8;       // A: row offset
    int at_k = (lane >> 4) * 8;                          // A: col offset
    int bt_n = (lane & 7) + ((lane & 16) ? 8 : 0);       // B: row offset
    int bt_k = ((lane >> 3) & 1) * 8;                    // B: col offset

    // ---- staging: chunk c (0..23) into stage buffer st ----
    auto stage = [&](int c, int st) {
        int chl = (c >= 12 ? c - 12 : c) * 32 + kq * 4;  // channel in [0,384)
        int ch  = chbase + chl;
        int f   = (chl & 127) >> 1;
        const float* tabBase = (c < 12) ? g_cos : g_sin;
#pragma unroll
        for (int pass = 0; pass < 2; pass++) {
            const float* src = pass == 0 ? g_q : g_k;
            int nb = pass == 0 ? nb_i : nb_j;
            __nv_bfloat16* Dh = smb + ((st * 4) + pass * 2) * SARR;
            __nv_bfloat16* Dl = Dh + SARR;
#pragma unroll
            for (int i = 0; i < 4; i++) {
                int r = rr + i * 32;
                int node = nb + r;
                const float* tb = tabBase + node * 192 + a * 64;
                float c0 = tb[f], c1 = tb[f + 1];
                float4 v = *(const float4*)(src + (size_t)node * MCH + ch);
                float x0 = v.x * c0, x1 = v.y * c0;
                float x2 = v.z * c1, x3 = v.w * c1;
                __nv_bfloat162 h01 = __floats2bfloat162_rn(x0, x1);
                __nv_bfloat162 h23 = __floats2bfloat162_rn(x2, x3);
                float2 g01 = __bfloat1622float2(h01);
                float2 g23 = __bfloat1622float2(h23);
                __nv_bfloat162 l01 = __floats2bfloat162_rn(x0 - g01.x, x1 - g01.y);
                __nv_bfloat162 l23 = __floats2bfloat162_rn(x2 - g23.x, x3 - g23.y);
                __nv_bfloat162* ph = (__nv_bfloat162*)(Dh + r * SPITCH + kq * 4);
                ph[0] = h01; ph[1] = h23;
                __nv_bfloat162* pl = (__nv_bfloat162*)(Dl + r * SPITCH + kq * 4);
                pl[0] = l01; pl[1] = l23;
            }
        }
    };

    // ---- mma over one staged 32-wide K chunk ----
    auto mma_stage = [&](int st) {
        const __nv_bfloat16* Ah = smb + (st * 4 + 0) * SARR;
        const __nv_bfloat16* Al = Ah + SARR;
        const __nv_bfloat16* Bh = Ah + 2 * SARR;
        const __nv_bfloat16* Bl = Ah + 3 * SARR;
#pragma unroll
        for (int k16 = 0; k16 < 2; k16++) {
            int kc = k16 * 16 + at_k;
            uint32_t ah[2][4], al[2][4];
#pragma unroll
            for (int mt = 0; mt < 2; mt++) {
                int row = wm * 32 + mt * 16 + at_r;
                ldsm4(ah[mt], cvsm(Ah + row * SPITCH + kc));
                ldsm4(al[mt], cvsm(Al + row * SPITCH + kc));
            }
            int kcb = k16 * 16 + bt_k;
#pragma unroll
            for (int np = 0; np < 4; np++) {
                int n = wn * 64 + np * 16 + bt_n;
                uint32_t bh[4], bl[4];
                ldsm4(bh, cvsm(Bh + n * SPITCH + kcb));
                ldsm4(bl, cvsm(Bl + n * SPITCH + kcb));
#pragma unroll
                for (int mt = 0; mt < 2; mt++) {
#pragma unroll
                    for (int nt = 0; nt < 2; nt++) {
                        float* d = acc[mt][np * 2 + nt];
                        mma16816(d, ah[mt], bh[nt * 2], bh[nt * 2 + 1]);
                        mma16816(d, ah[mt], bl[nt * 2], bl[nt * 2 + 1]);
                        mma16816(d, al[mt], bh[nt * 2], bh[nt * 2 + 1]);
                    }
                }
            }
        }
    };

    stage(0, 0);
    __syncthreads();
    for (int c = 0; c < 24; c++) {
        int st = c & 1;
        if (c + 1 < 24) stage(c + 1, st ^ 1);
        mma_stage(st);
        __syncthreads();
    }

    // ---- epilogue: write partial slab ----
    size_t base = ((size_t)sp * BB + b) * (NB * NB);
    int gr = blockIdx.x * 128 + wm * 32;
    int gc = blockIdx.y * 128 + wn * 64;
    int tr = lane >> 2, tc = (lane & 3) * 2;
#pragma unroll
    for (int mt = 0; mt < 2; mt++) {
#pragma unroll
        for (int nt = 0; nt < 8; nt++) {
            int r0 = gr + mt * 16 + tr;
            int cc = gc + nt * 8 + tc;
            float2 d01 = make_float2(acc[mt][nt][0], acc[mt][nt][1]);
            float2 d23 = make_float2(acc[mt][nt][2], acc[mt][nt][3]);
            *(float2*)(g_Spart + base + (size_t)r0 * NB + cc) = d01;
            *(float2*)(g_Spart + base + (size_t)(r0 + 8) * NB + cc) = d23;
        }
    }
}

// ---------------- kernel: slab reduce -----------------------------------------
__global__ void k_reduceS() {
    int i = blockIdx.x * 256 + threadIdx.x;
    const int SZ = BB * NB * NB;
    if (i >= SZ) return;
    float s = 0.0f;
#pragma unroll
    for (int sl = 0; sl < 9; sl++) s += g_Spart[(size_t)sl * SZ + i];
    g_S[i] = s * (1.0f / 3.0f);   // = 2 * grid_w (pairing factor * 1/6)
}

// ---------------- kernel: out = Sbar @ V (+mask) ------------------------------
__global__ void __launch_bounds__(256)
k_out(const int* __restrict__ bseg, const int* __restrict__ gmask,
      float* __restrict__ out) {
    extern __shared__ float sm[];
    float* Ss = sm;            // [64][68]
    float* Vs = sm + 64 * 68;  // [64][132]

    int b = blockIdx.z;
    int r0 = blockIdx.x * 64;
    int d0 = blockIdx.y * 128;
    int tid = threadIdx.x;
    int tx = tid & 15, ty = tid >> 4;

    unsigned long long acc[4][4];
#pragma unroll
    for (int i = 0; i < 4; i++)
#pragma unroll
        for (int j = 0; j < 4; j++) acc[i][j] = 0ull;

    int jg = tid & 15, rw = tid >> 4;
    int cg = tid & 31, k0 = tid >> 5;

    for (int jc = 0; jc < 4; jc++) {
        int j0 = jc * 64;
        __syncthreads();
#pragma unroll
        for (int i = 0; i < 4; i++) {
            int row = rw + i * 16;
            float4 v = *(const float4*)(g_S + ((size_t)b * NB + r0 + row) * NB + j0 + jg * 4);
            Ss[(jg * 4 + 0) * 68 + row] = v.x;
            Ss[(jg * 4 + 1) * 68 + row] = v.y;
            Ss[(jg * 4 + 2) * 68 + row] = v.z;
            Ss[(jg * 4 + 3) * 68 + row] = v.w;
        }
#pragma unroll
        for (int i = 0; i < 8; i++) {
            int kk = k0 + i * 8;
            *(float4*)(Vs + kk * 132 + cg * 4) =
                *(const float4*)(g_v + ((size_t)b * NB + j0 + kk) * MCH + d0 + cg * 4);
        }
        __syncthreads();
#pragma unroll 8
        for (int kk = 0; kk < 64; kk++) {
            float4 s4 = *(const float4*)(Ss + kk * 68 + ty * 4);
            ulonglong2 v0 = *(const ulonglong2*)(Vs + kk * 132 + tx * 8);
            ulonglong2 v1 = *(const ulonglong2*)(Vs + kk * 132 + tx * 8 + 4);
            unsigned long long bb0 = v0.x, bb1 = v0.y, bb2 = v1.x, bb3 = v1.y;
            unsigned long long av;
            av = splat2(s4.x); fma2(acc[0][0],av,bb0); fma2(acc[0][1],av,bb1); fma2(acc[0][2],av,bb2); fma2(acc[0][3],av,bb3);
            av = splat2(s4.y); fma2(acc[1][0],av,bb0); fma2(acc[1][1],av,bb1); fma2(acc[1][2],av,bb2); fma2(acc[1][3],av,bb3);
            av = splat2(s4.z); fma2(acc[2][0],av,bb0); fma2(acc[2][1],av,bb1); fma2(acc[2][2],av,bb2); fma2(acc[2][3],av,bb3);
            av = splat2(s4.w); fma2(acc[3][0],av,bb0); fma2(acc[3][1],av,bb1); fma2(acc[3][2],av,bb2); fma2(acc[3][3],av,bb3);
        }
    }

#pragma unroll
    for (int r = 0; r < 4; r++) {
        int node = b * NB + r0 + ty * 4 + r;
        bool mk = gmask[bseg[node]] != 0;
#pragma unroll
        for (int j = 0; j < 4; j++) {
            unsigned long long v = mk ? acc[r][j] : 0ull;
            *(unsigned long long*)(out + (size_t)node * MCH + d0 + tx * 8 + j * 2) = v;
        }
    }
}

// ---------------- launcher ----------------------------------------------------
extern "C" void kernel_launch(void* const* d_in, const int* in_sizes, int n_in,
                              void* d_out, int out_size) {
    const float* X   = (const float*)d_in[0];
    const float* pos = (const float*)d_in[1];
    const int* bseg  = (const int*)d_in[2];
    const int* gmask = (const int*)d_in[3];   // bool -> int32 in harness
    const float* Wq = (const float*)d_in[4];
    const float* bq = (const float*)d_in[5];
    const float* Wk = (const float*)d_in[6];
    const float* bk = (const float*)d_in[7];
    const float* Wv = (const float*)d_in[8];
    const float* bv = (const float*)d_in[9];
    float* out = (float*)d_out;

    cudaFuncSetAttribute(k_proj,  cudaFuncAttributeMaxDynamicSharedMemorySize, 33280);
    cudaFuncSetAttribute(k_score, cudaFuncAttributeMaxDynamicSharedMemorySize, 81920);
    cudaFuncSetAttribute(k_out,   cudaFuncAttributeMaxDynamicSharedMemorySize, 51200);

    k_cs<<<(NN * 3 * NFREQ + 255) / 256, 256>>>(pos);
    k_proj<<<dim3(160, 1, 9), 256, 33280>>>(X, Wq, bq, Wk, bk, Wv, bv);
    k_score<<<dim3(2, 2, BB * 9), 256, 81920>>>();
    k_reduceS<<<(BB * NB * NB) / 256, 256>>>();
    k_out<<<dim3(4, 9, BB), 256, 51200>>>(bseg, gmask, out);
}

// round 5
// speedup vs baseline: 2.2535x; 1.4397x over previous
#include <cuda_runtime.h>
#include <cuda_bf16.h>
#include <cstdint>

#define NN   4096
#define BB   16
#define NB   256      // nodes per batch
#define ND   9        // NUM_DEG
#define FF   128
#define MCH  1152     // 9*128
#define NFREQ 64

// ---------------- scratch (static device memory; no allocations) ------------
__device__ float g_q[NN * MCH];
__device__ float g_k[NN * MCH];
__device__ float g_v[NN * MCH];
__device__ float g_cos[NN * 3 * NFREQ];
__device__ float g_sin[NN * 3 * NFREQ];
__device__ float g_Spart[9u * BB * NB * NB];   // 9 partial slabs
__device__ float g_S[BB * NB * NB];

// ---------------- mma helpers -------------------------------------------------
__device__ __forceinline__ uint32_t cvsm(const void* p) {
    return (uint32_t)__cvta_generic_to_shared(p);
}
__device__ __forceinline__ void ldsm4(uint32_t* r, uint32_t addr) {
    asm volatile("ldmatrix.sync.aligned.m8n8.x4.shared.b16 {%0,%1,%2,%3}, [%4];"
                 : "=r"(r[0]), "=r"(r[1]), "=r"(r[2]), "=r"(r[3])
                 : "r"(addr));
}
__device__ __forceinline__ void mma16816(float* d, const uint32_t* a,
                                         uint32_t b0, uint32_t b1) {
    asm volatile(
        "mma.sync.aligned.m16n8k16.row.col.f32.bf16.bf16.f32 "
        "{%0,%1,%2,%3}, {%4,%5,%6,%7}, {%8,%9}, {%0,%1,%2,%3};"
        : "+f"(d[0]), "+f"(d[1]), "+f"(d[2]), "+f"(d[3])
        : "r"(a[0]), "r"(a[1]), "r"(a[2]), "r"(a[3]), "r"(b0), "r"(b1));
}
__device__ __forceinline__ void split2(float x0, float x1,
                                       __nv_bfloat162& h, __nv_bfloat162& l) {
    h = __floats2bfloat162_rn(x0, x1);
    float2 g = __bfloat1622float2(h);
    l = __floats2bfloat162_rn(x0 - g.x, x1 - g.y);
}

#define SPITCH 40           // bf16 elements per smem row (80 B, conflict-free)
#define SARR   (128 * SPITCH)

// mma over one staged 32-wide K chunk (4 arrays: Ah Al Bh Bl at smb_st)
__device__ __forceinline__ void mma_stage_fn(
    const __nv_bfloat16* smb_st, float acc[2][8][4],
    int wm, int wn, int at_r, int at_k, int bt_n, int bt_k) {
    const __nv_bfloat16* Ah = smb_st;
    const __nv_bfloat16* Al = Ah + SARR;
    const __nv_bfloat16* Bh = Ah + 2 * SARR;
    const __nv_bfloat16* Bl = Ah + 3 * SARR;
#pragma unroll
    for (int k16 = 0; k16 < 2; k16++) {
        int kc = k16 * 16 + at_k;
        uint32_t ah[2][4], al[2][4];
#pragma unroll
        for (int mt = 0; mt < 2; mt++) {
            int row = wm * 32 + mt * 16 + at_r;
            ldsm4(ah[mt], cvsm(Ah + row * SPITCH + kc));
            ldsm4(al[mt], cvsm(Al + row * SPITCH + kc));
        }
        int kcb = k16 * 16 + bt_k;
#pragma unroll
        for (int np = 0; np < 4; np++) {
            int n = wn * 64 + np * 16 + bt_n;
            uint32_t bh[4], bl[4];
            ldsm4(bh, cvsm(Bh + n * SPITCH + kcb));
            ldsm4(bl, cvsm(Bl + n * SPITCH + kcb));
#pragma unroll
            for (int mt = 0; mt < 2; mt++) {
#pragma unroll
                for (int nt = 0; nt < 2; nt++) {
                    float* d = acc[mt][np * 2 + nt];
                    mma16816(d, ah[mt], bh[nt * 2], bh[nt * 2 + 1]);
                    mma16816(d, ah[mt], bl[nt * 2], bl[nt * 2 + 1]);
                    mma16816(d, al[mt], bh[nt * 2], bh[nt * 2 + 1]);
                }
            }
        }
    }
}

// ---------------- kernel: cos/sin tables ------------------------------------
__global__ void k_cs(const float* __restrict__ pos) {
    int idx = blockIdx.x * 256 + threadIdx.x;
    if (idx >= NN * 3 * NFREQ) return;
    int c = idx & 63;
    int a = (idx >> 6) % 3;
    int n = idx / 192;
    float theta = (8.0f / (63.0f * 10.0f)) * (float)c;  // linspace(0,8,64)/10
    float ph = pos[n * 3 + a] * theta;
    float s, co;
    sincosf(ph, &s, &co);
    g_cos[idx] = co;
    g_sin[idx] = s;
}

// ---------------- kernel: q/k/v projections via hi/lo mma ---------------------
__global__ void __launch_bounds__(256, 2)
k_proj(const float* __restrict__ X,
       const float* __restrict__ Wq, const float* __restrict__ bq,
       const float* __restrict__ Wk, const float* __restrict__ bk,
       const float* __restrict__ Wv, const float* __restrict__ bv) {
    extern __shared__ unsigned char smraw[];
    __nv_bfloat16* smb = (__nv_bfloat16*)smraw;

    int z = blockIdx.z;
    int p = z / 3, l = z % 3;
    const int cnt = (l == 0) ? 1 : (l == 1 ? 3 : 5);
    const int m0  = (l == 0) ? 0 : (l == 1 ? 1 : 4);
    int ntiles = (NN * cnt) >> 7;
    if ((int)blockIdx.x >= ntiles) return;

    const float* W    = (p == 0 ? Wq : (p == 1 ? Wk : Wv)) + l * FF * FF;
    const float* bias = (p == 0 ? bq : (p == 1 ? bk : bv));
    float* dst = (p == 0 ? g_q : (p == 1 ? g_k : g_v));

    int row0 = blockIdx.x * 128;
    int tid = threadIdx.x;
    int wid = tid >> 5, lane = tid & 31;
    int wm = wid & 3, wn = wid >> 2;

    int kq = tid & 7, rr = tid >> 3;
    int kk = tid & 31, ng = tid >> 5;

    const float* arow[4];
#pragma unroll
    for (int i = 0; i < 4; i++) {
        int rg = row0 + rr + i * 32;
        int node = rg / cnt, mi = rg - node * cnt;
        arow[i] = X + ((size_t)node * ND + (m0 + mi)) * FF;
    }

    float acc[2][8][4];
#pragma unroll
    for (int mt = 0; mt < 2; mt++)
#pragma unroll
        for (int nt = 0; nt < 8; nt++)
#pragma unroll
            for (int e = 0; e < 4; e++) acc[mt][nt][e] = 0.0f;

    int at_r = (lane & 7) + ((lane >> 3) & 1) * 8;
    int at_k = (lane >> 4) * 8;
    int bt_n = (lane & 7) + ((lane & 16) ? 8 : 0);
    int bt_k = ((lane >> 3) & 1) * 8;

    auto stage = [&](int c, int st) {
        int f0 = c * 32;
        __nv_bfloat16* Ahd = smb + (st * 4 + 0) * SARR;
        __nv_bfloat16* Ald = Ahd + SARR;
#pragma unroll
        for (int i = 0; i < 4; i++) {
            int r = rr + i * 32;
            float4 v = *(const float4*)(arow[i] + f0 + kq * 4);
            __nv_bfloat162 h01, l01, h23, l23;
            split2(v.x, v.y, h01, l01);
            split2(v.z, v.w, h23, l23);
            __nv_bfloat162* ph = (__nv_bfloat162*)(Ahd + r * SPITCH + kq * 4);
            ph[0] = h01; ph[1] = h23;
            __nv_bfloat162* pl = (__nv_bfloat162*)(Ald + r * SPITCH + kq * 4);
            pl[0] = l01; pl[1] = l23;
        }
        __nv_bfloat16* Bhd = smb + (st * 4 + 2) * SARR;
        __nv_bfloat16* Bld = Bhd + SARR;
#pragma unroll
        for (int j = 0; j < 4; j++) {
            int n0 = ng * 16 + j * 4;
            float4 w = *(const float4*)(W + (size_t)(f0 + kk) * 128 + n0);
            float ws[4] = {w.x, w.y, w.z, w.w};
#pragma unroll
            for (int e = 0; e < 4; e++) {
                __nv_bfloat16 h = __float2bfloat16_rn(ws[e]);
                __nv_bfloat16 lo = __float2bfloat16_rn(ws[e] - __bfloat162float(h));
                Bhd[(n0 + e) * SPITCH + kk] = h;
                Bld[(n0 + e) * SPITCH + kk] = lo;
            }
        }
    };

    stage(0, 0);
    __syncthreads();
    for (int c = 0; c < 4; c++) {
        int st = c & 1;
        if (c + 1 < 4) stage(c + 1, st ^ 1);
        mma_stage_fn(smb + st * 4 * SARR, acc, wm, wn, at_r, at_k, bt_n, bt_k);
        __syncthreads();
    }

    int tr = lane >> 2, tc = (lane & 3) * 2;
#pragma unroll
    for (int mt = 0; mt < 2; mt++) {
#pragma unroll
        for (int half = 0; half < 2; half++) {
            int rgl = row0 + wm * 32 + mt * 16 + tr + half * 8;
            int node = rgl / cnt, mi = rgl - node * cnt;
            size_t obase = (size_t)node * MCH + (m0 + mi) * FF;
#pragma unroll
            for (int nt = 0; nt < 8; nt++) {
                int col = wn * 64 + nt * 8 + tc;
                float d0 = acc[mt][nt][half * 2 + 0];
                float d1 = acc[mt][nt][half * 2 + 1];
                if (l == 0) { d0 += bias[col]; d1 += bias[col + 1]; }
                *(float2*)(dst + obase + col) = make_float2(d0, d1);
            }
        }
    }
}

// ---------------- kernel: score partials via bf16 hi/lo mma.sync --------------
__global__ void __launch_bounds__(256, 2)
k_score() {
    extern __shared__ unsigned char smraw[];
    __nv_bfloat16* smb = (__nv_bfloat16*)smraw;

    int zz = blockIdx.z;
    int b = zz / 9, sp = zz - b * 9;
    int a = sp / 3, mc = sp - a * 3;
    int nb_i = b * NB + blockIdx.x * 128;
    int nb_j = b * NB + blockIdx.y * 128;
    int tid = threadIdx.x;
    int wid = tid >> 5, lane = tid & 31;
    int wm = wid & 3, wn = wid >> 2;

    float acc[2][8][4];
#pragma unroll
    for (int mt = 0; mt < 2; mt++)
#pragma unroll
        for (int nt = 0; nt < 8; nt++)
#pragma unroll
            for (int e = 0; e < 4; e++) acc[mt][nt][e] = 0.0f;

    int kq = tid & 7, rr = tid >> 3;
    int chbase = mc * 384;

    int at_r = (lane & 7) + ((lane >> 3) & 1) * 8;
    int at_k = (lane >> 4) * 8;
    int bt_n = (lane & 7) + ((lane & 16) ? 8 : 0);
    int bt_k = ((lane >> 3) & 1) * 8;

    auto stage = [&](int c, int st) {
        int chl = (c >= 12 ? c - 12 : c) * 32 + kq * 4;
        int ch  = chbase + chl;
        int f   = (chl & 127) >> 1;
        const float* tabBase = (c < 12) ? g_cos : g_sin;
#pragma unroll
        for (int pass = 0; pass < 2; pass++) {
            const float* src = pass == 0 ? g_q : g_k;
            int nb = pass == 0 ? nb_i : nb_j;
            __nv_bfloat16* Dh = smb + ((st * 4) + pass * 2) * SARR;
            __nv_bfloat16* Dl = Dh + SARR;
#pragma unroll
            for (int i = 0; i < 4; i++) {
                int r = rr + i * 32;
                int node = nb + r;
                const float* tb = tabBase + node * 192 + a * 64;
                float c0 = tb[f], c1 = tb[f + 1];
                float4 v = *(const float4*)(src + (size_t)node * MCH + ch);
                __nv_bfloat162 h01, l01, h23, l23;
                split2(v.x * c0, v.y * c0, h01, l01);
                split2(v.z * c1, v.w * c1, h23, l23);
                __nv_bfloat162* ph = (__nv_bfloat162*)(Dh + r * SPITCH + kq * 4);
                ph[0] = h01; ph[1] = h23;
                __nv_bfloat162* pl = (__nv_bfloat162*)(Dl + r * SPITCH + kq * 4);
                pl[0] = l01; pl[1] = l23;
            }
        }
    };

    stage(0, 0);
    __syncthreads();
    for (int c = 0; c < 24; c++) {
        int st = c & 1;
        if (c + 1 < 24) stage(c + 1, st ^ 1);
        mma_stage_fn(smb + st * 4 * SARR, acc, wm, wn, at_r, at_k, bt_n, bt_k);
        __syncthreads();
    }

    size_t base = ((size_t)sp * BB + b) * (NB * NB);
    int gr = blockIdx.x * 128 + wm * 32;
    int gc = blockIdx.y * 128 + wn * 64;
    int tr = lane >> 2, tc = (lane & 3) * 2;
#pragma unroll
    for (int mt = 0; mt < 2; mt++) {
#pragma unroll
        for (int nt = 0; nt < 8; nt++) {
            int r0 = gr + mt * 16 + tr;
            int cc = gc + nt * 8 + tc;
            float2 d01 = make_float2(acc[mt][nt][0], acc[mt][nt][1]);
            float2 d23 = make_float2(acc[mt][nt][2], acc[mt][nt][3]);
            *(float2*)(g_Spart + base + (size_t)r0 * NB + cc) = d01;
            *(float2*)(g_Spart + base + (size_t)(r0 + 8) * NB + cc) = d23;
        }
    }
}

// ---------------- kernel: slab reduce -----------------------------------------
__global__ void k_reduceS() {
    int i = blockIdx.x * 256 + threadIdx.x;
    const int SZ = BB * NB * NB;
    if (i >= SZ) return;
    float s = 0.0f;
#pragma unroll
    for (int sl = 0; sl < 9; sl++) s += g_Spart[(size_t)sl * SZ + i];
    g_S[i] = s * (1.0f / 3.0f);   // = 2 * grid_w (pairing factor * 1/6)
}

// ---------------- kernel: out = Sbar @ V (+mask) via hi/lo mma -----------------
__global__ void __launch_bounds__(256, 2)
k_out(const int* __restrict__ bseg, const int* __restrict__ gmask,
      float* __restrict__ out) {
    extern __shared__ unsigned char smraw[];
    __nv_bfloat16* smb = (__nv_bfloat16*)smraw;

    int b = blockIdx.z;
    int r0 = blockIdx.x * 128;
    int d0 = blockIdx.y * 128;
    int tid = threadIdx.x;
    int wid = tid >> 5, lane = tid & 31;
    int wm = wid & 3, wn = wid >> 2;

    int kq = tid & 7, rr = tid >> 3;
    int kk = tid & 31, ng = tid >> 5;

    float acc[2][8][4];
#pragma unroll
    for (int mt = 0; mt < 2; mt++)
#pragma unroll
        for (int nt = 0; nt < 8; nt++)
#pragma unroll
            for (int e = 0; e < 4; e++) acc[mt][nt][e] = 0.0f;

    int at_r = (lane & 7) + ((lane >> 3) & 1) * 8;
    int at_k = (lane >> 4) * 8;
    int bt_n = (lane & 7) + ((lane & 16) ? 8 : 0);
    int bt_k = ((lane >> 3) & 1) * 8;

    auto stage = [&](int c, int st) {
        int j0 = c * 32;
        __nv_bfloat16* Ahd = smb + (st * 4 + 0) * SARR;
        __nv_bfloat16* Ald = Ahd + SARR;
#pragma unroll
        for (int i = 0; i < 4; i++) {
            int r = rr + i * 32;
            float4 v = *(const float4*)(g_S + ((size_t)b * NB + r0 + r) * NB + j0 + kq * 4);
            __nv_bfloat162 h01, l01, h23, l23;
            split2(v.x, v.y, h01, l01);
            split2(v.z, v.w, h23, l23);
            __nv_bfloat162* ph = (__nv_bfloat162*)(Ahd + r * SPITCH + kq * 4);
            ph[0] = h01; ph[1] = h23;
            __nv_bfloat162* pl = (__nv_bfloat162*)(Ald + r * SPITCH + kq * 4);
            pl[0] = l01; pl[1] = l23;
        }
        __nv_bfloat16* Bhd = smb + (st * 4 + 2) * SARR;
        __nv_bfloat16* Bld = Bhd + SARR;
#pragma unroll
        for (int j = 0; j < 4; j++) {
            int n0 = ng * 16 + j * 4;
            float4 v = *(const float4*)(g_v + ((size_t)(b * NB + j0 + kk)) * MCH + d0 + n0);
            float vs[4] = {v.x, v.y, v.z, v.w};
#pragma unroll
            for (int e = 0; e < 4; e++) {
                __nv_bfloat16 h = __float2bfloat16_rn(vs[e]);
                __nv_bfloat16 lo = __float2bfloat16_rn(vs[e] - __bfloat162float(h));
                Bhd[(n0 + e) * SPITCH + kk] = h;
                Bld[(n0 + e) * SPITCH + kk] = lo;
            }
        }
    };

    stage(0, 0);
    __syncthreads();
    for (int c = 0; c < 8; c++) {
        int st = c & 1;
        if (c + 1 < 8) stage(c + 1, st ^ 1);
        mma_stage_fn(smb + st * 4 * SARR, acc, wm, wn, at_r, at_k, bt_n, bt_k);
        __syncthreads();
    }

    int tr = lane >> 2, tc = (lane & 3) * 2;
#pragma unroll
    for (int mt = 0; mt < 2; mt++) {
#pragma unroll
        for (int half = 0; half < 2; half++) {
            int node = b * NB + r0 + wm * 32 + mt * 16 + tr + half * 8;
            bool mk = gmask[bseg[node]] != 0;
#pragma unroll
            for (int nt = 0; nt < 8; nt++) {
                int col = wn * 64 + nt * 8 + tc;
                float o0 = mk ? acc[mt][nt][half * 2 + 0] : 0.0f;
                float o1 = mk ? acc[mt][nt][half * 2 + 1] : 0.0f;
                *(float2*)(out + (size_t)node * MCH + d0 + col) = make_float2(o0, o1);
            }
        }
    }
}

// ---------------- launcher ----------------------------------------------------
extern "C" void kernel_launch(void* const* d_in, const int* in_sizes, int n_in,
                              void* d_out, int out_size) {
    const float* X   = (const float*)d_in[0];
    const float* pos = (const float*)d_in[1];
    const int* bseg  = (const int*)d_in[2];
    const int* gmask = (const int*)d_in[3];   // bool -> int32 in harness
    const float* Wq = (const float*)d_in[4];
    const float* bq = (const float*)d_in[5];
    const float* Wk = (const float*)d_in[6];
    const float* bk = (const float*)d_in[7];
    const float* Wv = (const float*)d_in[8];
    const float* bv = (const float*)d_in[9];
    float* out = (float*)d_out;

    cudaFuncSetAttribute(k_proj,  cudaFuncAttributeMaxDynamicSharedMemorySize, 81920);
    cudaFuncSetAttribute(k_score, cudaFuncAttributeMaxDynamicSharedMemorySize, 81920);
    cudaFuncSetAttribute(k_out,   cudaFuncAttributeMaxDynamicSharedMemorySize, 81920);

    k_cs<<<(NN * 3 * NFREQ + 255) / 256, 256>>>(pos);
    k_proj<<<dim3(160, 1, 9), 256, 81920>>>(X, Wq, bq, Wk, bk, Wv, bv);
    k_score<<<dim3(2, 2, BB * 9), 256, 81920>>>();
    k_reduceS<<<(BB * NB * NB) / 256, 256>>>();
    k_out<<<dim3(2, 9, BB), 256, 81920>>>(bseg, gmask, out);
}

// round 7
// speedup vs baseline: 2.2942x; 1.0180x over previous
#include <cuda_runtime.h>
#include <cuda_bf16.h>
#include <cstdint>

#define NN   4096
#define BB   16
#define NB   256      // nodes per batch
#define ND   9        // NUM_DEG
#define FF   128
#define MCH  1152     // 9*128
#define NFREQ 64
#define SZSLAB (BB * NB * NB)

// ---------------- scratch (static device memory; no allocations) ------------
__device__ float g_q[NN * MCH];
__device__ float g_k[NN * MCH];
__device__ float g_v[NN * MCH];
__device__ float g_cos[NN * 3 * NFREQ];
__device__ float g_sin[NN * 3 * NFREQ];
__device__ float g_Spart[9u * SZSLAB];   // 9 partial slabs

// ---------------- helpers ------------------------------------------------------
__device__ __forceinline__ uint32_t cvsm(const void* p) {
    return (uint32_t)__cvta_generic_to_shared(p);
}
__device__ __forceinline__ void split2(float x0, float x1,
                                       __nv_bfloat162& h, __nv_bfloat162& l) {
    h = __floats2bfloat162_rn(x0, x1);
    float2 g = __bfloat1622float2(h);
    l = __floats2bfloat162_rn(x0 - g.x, x1 - g.y);
}
__device__ __forceinline__ void ldsm4(uint32_t* r, uint32_t addr) {
    asm volatile("ldmatrix.sync.aligned.m8n8.x4.shared.b16 {%0,%1,%2,%3}, [%4];"
                 : "=r"(r[0]), "=r"(r[1]), "=r"(r[2]), "=r"(r[3])
                 : "r"(addr));
}
__device__ __forceinline__ void mma16816(float* d, const uint32_t* a,
                                         uint32_t b0, uint32_t b1) {
    asm volatile(
        "mma.sync.aligned.m16n8k16.row.col.f32.bf16.bf16.f32 "
        "{%0,%1,%2,%3}, {%4,%5,%6,%7}, {%8,%9}, {%0,%1,%2,%3};"
        : "+f"(d[0]), "+f"(d[1]), "+f"(d[2]), "+f"(d[3])
        : "r"(a[0]), "r"(a[1]), "r"(a[2]), "r"(a[3]), "r"(b0), "r"(b1));
}

// ---- generic hi/lo mma over a staged chunk; NK16 k16-subchunks, given pitch ----
template <int PITCH, int NK16>
__device__ __forceinline__ void mma_chunk(
    const __nv_bfloat16* base, float acc[2][8][4],
    int wm, int wn, int at_r, int at_k, int bt_n, int bt_k) {
    const int ARR = 128 * PITCH;
    const __nv_bfloat16* Ah = base;
    const __nv_bfloat16* Al = Ah + ARR;
    const __nv_bfloat16* Bh = Ah + 2 * ARR;
    const __nv_bfloat16* Bl = Ah + 3 * ARR;
#pragma unroll
    for (int k16 = 0; k16 < NK16; k16++) {
        int kc = k16 * 16 + at_k;
        uint32_t ah[2][4], al[2][4];
#pragma unroll
        for (int mt = 0; mt < 2; mt++) {
            int row = wm * 32 + mt * 16 + at_r;
            ldsm4(ah[mt], cvsm(Ah + row * PITCH + kc));
            ldsm4(al[mt], cvsm(Al + row * PITCH + kc));
        }
        int kcb = k16 * 16 + bt_k;
#pragma unroll
        for (int np = 0; np < 4; np++) {
            int n = wn * 64 + np * 16 + bt_n;
            uint32_t bh[4], bl[4];
            ldsm4(bh, cvsm(Bh + n * PITCH + kcb));
            ldsm4(bl, cvsm(Bl + n * PITCH + kcb));
#pragma unroll
            for (int mt = 0; mt < 2; mt++) {
#pragma unroll
                for (int nt = 0; nt < 2; nt++) {
                    float* d = acc[mt][np * 2 + nt];
                    mma16816(d, ah[mt], bh[nt * 2], bh[nt * 2 + 1]);
                    mma16816(d, ah[mt], bl[nt * 2], bl[nt * 2 + 1]);
                    mma16816(d, al[mt], bh[nt * 2], bh[nt * 2 + 1]);
                }
            }
        }
    }
}

#define SPITCH 40
#define SARR   (128 * SPITCH)

// ---------------- kernel: cos/sin tables ------------------------------------
__global__ void k_cs(const float* __restrict__ pos) {
    int idx = blockIdx.x * 256 + threadIdx.x;
    if (idx >= NN * 3 * NFREQ) return;
    int c = idx & 63;
    int a = (idx >> 6) % 3;
    int n = idx / 192;
    float theta = (8.0f / (63.0f * 10.0f)) * (float)c;
    float ph = pos[n * 3 + a] * theta;
    float s, co;
    sincosf(ph, &s, &co);
    g_cos[idx] = co;
    g_sin[idx] = s;
}

// ---------------- kernel: q/k/v projections via hi/lo mma.sync ----------------
__global__ void __launch_bounds__(256, 2)
k_proj(const float* __restrict__ X,
       const float* __restrict__ Wq, const float* __restrict__ bq,
       const float* __restrict__ Wk, const float* __restrict__ bk,
       const float* __restrict__ Wv, const float* __restrict__ bv) {
    extern __shared__ unsigned char smraw[];
    __nv_bfloat16* smb = (__nv_bfloat16*)smraw;

    int z = blockIdx.z;
    int p = z / 3, l = z % 3;
    const int cnt = (l == 0) ? 1 : (l == 1 ? 3 : 5);
    const int m0  = (l == 0) ? 0 : (l == 1 ? 1 : 4);
    int ntiles = (NN * cnt) >> 7;
    if ((int)blockIdx.x >= ntiles) return;

    const float* W    = (p == 0 ? Wq : (p == 1 ? Wk : Wv)) + l * FF * FF;
    const float* bias = (p == 0 ? bq : (p == 1 ? bk : bv));
    float* dst = (p == 0 ? g_q : (p == 1 ? g_k : g_v));

    int row0 = blockIdx.x * 128;
    int tid = threadIdx.x;
    int wid = tid >> 5, lane = tid & 31;
    int wm = wid & 3, wn = wid >> 2;
    int kq = tid & 7, rr = tid >> 3;
    int kk = tid & 31, ng = tid >> 5;

    const float* arow[4];
#pragma unroll
    for (int i = 0; i < 4; i++) {
        int rg = row0 + rr + i * 32;
        int node = rg / cnt, mi = rg - node * cnt;
        arow[i] = X + ((size_t)node * ND + (m0 + mi)) * FF;
    }

    float acc[2][8][4];
#pragma unroll
    for (int mt = 0; mt < 2; mt++)
#pragma unroll
        for (int nt = 0; nt < 8; nt++)
#pragma unroll
            for (int e = 0; e < 4; e++) acc[mt][nt][e] = 0.0f;

    int at_r = (lane & 7) + ((lane >> 3) & 1) * 8;
    int at_k = (lane >> 4) * 8;
    int bt_n = (lane & 7) + ((lane & 16) ? 8 : 0);
    int bt_k = ((lane >> 3) & 1) * 8;

    auto stage = [&](int c, int st) {
        int f0 = c * 32;
        __nv_bfloat16* Ahd = smb + (st * 4 + 0) * SARR;
        __nv_bfloat16* Ald = Ahd + SARR;
#pragma unroll
        for (int i = 0; i < 4; i++) {
            int r = rr + i * 32;
            float4 v = *(const float4*)(arow[i] + f0 + kq * 4);
            __nv_bfloat162 h01, l01, h23, l23;
            split2(v.x, v.y, h01, l01);
            split2(v.z, v.w, h23, l23);
            __nv_bfloat162* ph = (__nv_bfloat162*)(Ahd + r * SPITCH + kq * 4);
            ph[0] = h01; ph[1] = h23;
            __nv_bfloat162* pl = (__nv_bfloat162*)(Ald + r * SPITCH + kq * 4);
            pl[0] = l01; pl[1] = l23;
        }
        __nv_bfloat16* Bhd = smb + (st * 4 + 2) * SARR;
        __nv_bfloat16* Bld = Bhd + SARR;
#pragma unroll
        for (int j = 0; j < 4; j++) {
            int n0 = ng * 16 + j * 4;
            float4 w = *(const float4*)(W + (size_t)(f0 + kk) * 128 + n0);
            float ws[4] = {w.x, w.y, w.z, w.w};
#pragma unroll
            for (int e = 0; e < 4; e++) {
                __nv_bfloat16 h = __float2bfloat16_rn(ws[e]);
                __nv_bfloat16 lo = __float2bfloat16_rn(ws[e] - __bfloat162float(h));
                Bhd[(n0 + e) * SPITCH + kk] = h;
                Bld[(n0 + e) * SPITCH + kk] = lo;
            }
        }
    };

    stage(0, 0);
    __syncthreads();
    for (int c = 0; c < 4; c++) {
        int st = c & 1;
        if (c + 1 < 4) stage(c + 1, st ^ 1);
        mma_chunk<SPITCH, 2>(smb + st * 4 * SARR, acc, wm, wn, at_r, at_k, bt_n, bt_k);
        __syncthreads();
    }

    int tr = lane >> 2, tc = (lane & 3) * 2;
#pragma unroll
    for (int mt = 0; mt < 2; mt++) {
#pragma unroll
        for (int half = 0; half < 2; half++) {
            int rgl = row0 + wm * 32 + mt * 16 + tr + half * 8;
            int node = rgl / cnt, mi = rgl - node * cnt;
            size_t obase = (size_t)node * MCH + (m0 + mi) * FF;
#pragma unroll
            for (int nt = 0; nt < 8; nt++) {
                int col = wn * 64 + nt * 8 + tc;
                float d0 = acc[mt][nt][half * 2 + 0];
                float d1 = acc[mt][nt][half * 2 + 1];
                if (l == 0) { d0 += bias[col]; d1 += bias[col + 1]; }
                *(float2*)(dst + obase + col) = make_float2(d0, d1);
            }
        }
    }
}

// ---------------- kernel: score partials, merged cos/sin K=64 stages ----------
// grid: x=ti(2), y=tj(2), z = b*9 + (a*3+mc). 12 stages; each stage stages a
// 128x64 tile per operand array: cols [0,32)=cos-scaled, [32,64)=sin-scaled,
// so each q/k float4 is loaded from L2 exactly once.
#define KPITCH 72
#define KARR   (128 * KPITCH)
#define KS_SMEM (4 * KARR * 2)   // 73728 bytes

__global__ void __launch_bounds__(256, 2)
k_score() {
    extern __shared__ unsigned char smraw[];
    __nv_bfloat16* smb = (__nv_bfloat16*)smraw;

    int zz = blockIdx.z;
    int b = zz / 9, sp = zz - b * 9;
    int a = sp / 3, mc = sp - a * 3;
    int nb_i = b * NB + blockIdx.x * 128;
    int nb_j = b * NB + blockIdx.y * 128;
    int tid = threadIdx.x;
    int wid = tid >> 5, lane = tid & 31;
    int wm = wid & 3, wn = wid >> 2;
    int kq = tid & 7, rr = tid >> 3;
    int chbase = mc * 384;

    float acc[2][8][4];
#pragma unroll
    for (int mt = 0; mt < 2; mt++)
#pragma unroll
        for (int nt = 0; nt < 8; nt++)
#pragma unroll
            for (int e = 0; e < 4; e++) acc[mt][nt][e] = 0.0f;

    int at_r = (lane & 7) + ((lane >> 3) & 1) * 8;
    int at_k = (lane >> 4) * 8;
    int bt_n = (lane & 7) + ((lane & 16) ? 8 : 0);
    int bt_k = ((lane >> 3) & 1) * 8;

    for (int c = 0; c < 12; c++) {
        int chl = c * 32 + kq * 4;
        int ch  = chbase + chl;
        int f   = (chl & 127) >> 1;
#pragma unroll
        for (int pass = 0; pass < 2; pass++) {
            const float* src = pass == 0 ? g_q : g_k;
            int nb = pass == 0 ? nb_i : nb_j;
            __nv_bfloat16* Dh = smb + (pass * 2) * KARR;
            __nv_bfloat16* Dl = Dh + KARR;
#pragma unroll
            for (int i = 0; i < 4; i++) {
                int r = rr + i * 32;
                int node = nb + r;
                const float* tc = g_cos + node * 192 + a * 64 + f;
                const float* ts = g_sin + node * 192 + a * 64 + f;
                float c0 = tc[0], c1 = tc[1];
                float s0 = ts[0], s1 = ts[1];
                float4 v = *(const float4*)(src + (size_t)node * MCH + ch);
                __nv_bfloat162 hc01, lc01, hc23, lc23, hs01, ls01, hs23, ls23;
                split2(v.x * c0, v.y * c0, hc01, lc01);
                split2(v.z * c1, v.w * c1, hc23, lc23);
                split2(v.x * s0, v.y * s0, hs01, ls01);
                split2(v.z * s1, v.w * s1, hs23, ls23);
                __nv_bfloat162* phc = (__nv_bfloat162*)(Dh + r * KPITCH + kq * 4);
                phc[0] = hc01; phc[1] = hc23;
                __nv_bfloat162* phs = (__nv_bfloat162*)(Dh + r * KPITCH + 32 + kq * 4);
                phs[0] = hs01; phs[1] = hs23;
                __nv_bfloat162* plc = (__nv_bfloat162*)(Dl + r * KPITCH + kq * 4);
                plc[0] = lc01; plc[1] = lc23;
                __nv_bfloat162* pls = (__nv_bfloat162*)(Dl + r * KPITCH + 32 + kq * 4);
                pls[0] = ls01; pls[1] = ls23;
            }
        }
        __syncthreads();
        mma_chunk<KPITCH, 4>(smb, acc, wm, wn, at_r, at_k, bt_n, bt_k);
        __syncthreads();
    }

    size_t base = ((size_t)sp * BB + b) * (NB * NB);
    int gr = blockIdx.x * 128 + wm * 32;
    int gc = blockIdx.y * 128 + wn * 64;
    int tr = lane >> 2, tc2 = (lane & 3) * 2;
#pragma unroll
    for (int mt = 0; mt < 2; mt++) {
#pragma unroll
        for (int nt = 0; nt < 8; nt++) {
            int r0 = gr + mt * 16 + tr;
            int cc = gc + nt * 8 + tc2;
            float2 d01 = make_float2(acc[mt][nt][0], acc[mt][nt][1]);
            float2 d23 = make_float2(acc[mt][nt][2], acc[mt][nt][3]);
            *(float2*)(g_Spart + base + (size_t)r0 * NB + cc) = d01;
            *(float2*)(g_Spart + base + (size_t)(r0 + 8) * NB + cc) = d23;
        }
    }
}

// ---------------- kernel: out = (sum slabs /3) @ V (+mask), hi/lo mma.sync ----
__global__ void __launch_bounds__(256, 2)
k_out(const int* __restrict__ bseg, const int* __restrict__ gmask,
      float* __restrict__ out) {
    extern __shared__ unsigned char smraw[];
    __nv_bfloat16* smb = (__nv_bfloat16*)smraw;

    int b = blockIdx.z;
    int r0 = blockIdx.x * 128;
    int d0 = blockIdx.y * 128;
    int tid = threadIdx.x;
    int wid = tid >> 5, lane = tid & 31;
    int wm = wid & 3, wn = wid >> 2;
    int kq = tid & 7, rr = tid >> 3;
    int kk = tid & 31, ng = tid >> 5;

    float acc[2][8][4];
#pragma unroll
    for (int mt = 0; mt < 2; mt++)
#pragma unroll
        for (int nt = 0; nt < 8; nt++)
#pragma unroll
            for (int e = 0; e < 4; e++) acc[mt][nt][e] = 0.0f;

    int at_r = (lane & 7) + ((lane >> 3) & 1) * 8;
    int at_k = (lane >> 4) * 8;
    int bt_n = (lane & 7) + ((lane & 16) ? 8 : 0);
    int bt_k = ((lane >> 3) & 1) * 8;

    auto stage = [&](int c, int st) {
        int j0 = c * 32;
        __nv_bfloat16* Ahd = smb + (st * 4 + 0) * SARR;
        __nv_bfloat16* Ald = Ahd + SARR;
#pragma unroll
        for (int i = 0; i < 4; i++) {
            int r = rr + i * 32;
            const float* Sp = g_Spart + (size_t)b * (NB * NB) +
                              (size_t)(r0 + r) * NB + j0 + kq * 4;
            float4 s4 = *(const float4*)Sp;
#pragma unroll
            for (int sl = 1; sl < 9; sl++) {
                float4 t = *(const float4*)(Sp + (size_t)sl * SZSLAB);
                s4.x += t.x; s4.y += t.y; s4.z += t.z; s4.w += t.w;
            }
            s4.x *= (1.0f / 3.0f); s4.y *= (1.0f / 3.0f);
            s4.z *= (1.0f / 3.0f); s4.w *= (1.0f / 3.0f);
            __nv_bfloat162 h01, l01, h23, l23;
            split2(s4.x, s4.y, h01, l01);
            split2(s4.z, s4.w, h23, l23);
            __nv_bfloat162* ph = (__nv_bfloat162*)(Ahd + r * SPITCH + kq * 4);
            ph[0] = h01; ph[1] = h23;
            __nv_bfloat162* pl = (__nv_bfloat162*)(Ald + r * SPITCH + kq * 4);
            pl[0] = l01; pl[1] = l23;
        }
        __nv_bfloat16* Bhd = smb + (st * 4 + 2) * SARR;
        __nv_bfloat16* Bld = Bhd + SARR;
#pragma unroll
        for (int j = 0; j < 4; j++) {
            int n0 = ng * 16 + j * 4;
            float4 v = *(const float4*)(g_v + ((size_t)(b * NB + j0 + kk)) * MCH + d0 + n0);
            float vs[4] = {v.x, v.y, v.z, v.w};
#pragma unroll
            for (int e = 0; e < 4; e++) {
                __nv_bfloat16 h = __float2bfloat16_rn(vs[e]);
                __nv_bfloat16 lo = __float2bfloat16_rn(vs[e] - __bfloat162float(h));
                Bhd[(n0 + e) * SPITCH + kk] = h;
                Bld[(n0 + e) * SPITCH + kk] = lo;
            }
        }
    };

    stage(0, 0);
    __syncthreads();
    for (int c = 0; c < 8; c++) {
        int st = c & 1;
        if (c + 1 < 8) stage(c + 1, st ^ 1);
        mma_chunk<SPITCH, 2>(smb + st * 4 * SARR, acc, wm, wn, at_r, at_k, bt_n, bt_k);
        __syncthreads();
    }

    int tr = lane >> 2, tc = (lane & 3) * 2;
#pragma unroll
    for (int mt = 0; mt < 2; mt++) {
#pragma unroll
        for (int half = 0; half < 2; half++) {
            int node = b * NB + r0 + wm * 32 + mt * 16 + tr + half * 8;
            bool mk = gmask[bseg[node]] != 0;
#pragma unroll
            for (int nt = 0; nt < 8; nt++) {
                int col = wn * 64 + nt * 8 + tc;
                float o0 = mk ? acc[mt][nt][half * 2 + 0] : 0.0f;
                float o1 = mk ? acc[mt][nt][half * 2 + 1] : 0.0f;
                *(float2*)(out + (size_t)node * MCH + d0 + col) = make_float2(o0, o1);
            }
        }
    }
}

// ---------------- launcher ----------------------------------------------------
extern "C" void kernel_launch(void* const* d_in, const int* in_sizes, int n_in,
                              void* d_out, int out_size) {
    const float* X   = (const float*)d_in[0];
    const float* pos = (const float*)d_in[1];
    const int* bseg  = (const int*)d_in[2];
    const int* gmask = (const int*)d_in[3];   // bool -> int32 in harness
    const float* Wq = (const float*)d_in[4];
    const float* bq = (const float*)d_in[5];
    const float* Wk = (const float*)d_in[6];
    const float* bk = (const float*)d_in[7];
    const float* Wv = (const float*)d_in[8];
    const float* bv = (const float*)d_in[9];
    float* out = (float*)d_out;

    cudaFuncSetAttribute(k_proj,  cudaFuncAttributeMaxDynamicSharedMemorySize, 81920);
    cudaFuncSetAttribute(k_score, cudaFuncAttributeMaxDynamicSharedMemorySize, KS_SMEM);
    cudaFuncSetAttribute(k_out,   cudaFuncAttributeMaxDynamicSharedMemorySize, 81920);

    k_cs<<<(NN * 3 * NFREQ + 255) / 256, 256>>>(pos);
    k_proj<<<dim3(160, 1, 9), 256, 81920>>>(X, Wq, bq, Wk, bk, Wv, bv);
    k_score<<<dim3(2, 2, BB * 9), 256, KS_SMEM>>>();
    k_out<<<dim3(2, 9, BB), 256, 81920>>>(bseg, gmask, out);
}

// round 8
// speedup vs baseline: 2.8667x; 1.2496x over previous
#include <cuda_runtime.h>
#include <cuda_bf16.h>
#include <cuda_fp16.h>
#include <cstdint>

#define NN   4096
#define BB   16
#define NB   256      // nodes per batch
#define ND   9        // NUM_DEG
#define FF   128
#define MCH  1152     // 9*128
#define NFREQ 64
#define SZSLAB (BB * NB * NB)

// ---------------- scratch (static device memory; no allocations) ------------
__device__ float g_q[NN * MCH];
__device__ float g_k[NN * MCH];
__device__ float g_v[NN * MCH];
__device__ float g_cos[NN * 3 * NFREQ];
__device__ float g_sin[NN * 3 * NFREQ];
__device__ float g_Spart[9u * SZSLAB];   // 9 partial slabs
__device__ float g_S[SZSLAB];

// ---------------- helpers ------------------------------------------------------
__device__ __forceinline__ uint32_t cvsm(const void* p) {
    return (uint32_t)__cvta_generic_to_shared(p);
}
__device__ __forceinline__ void split2(float x0, float x1,
                                       __nv_bfloat162& h, __nv_bfloat162& l) {
    h = __floats2bfloat162_rn(x0, x1);
    float2 g = __bfloat1622float2(h);
    l = __floats2bfloat162_rn(x0 - g.x, x1 - g.y);
}
__device__ __forceinline__ void ldsm4(uint32_t* r, uint32_t addr) {
    asm volatile("ldmatrix.sync.aligned.m8n8.x4.shared.b16 {%0,%1,%2,%3}, [%4];"
                 : "=r"(r[0]), "=r"(r[1]), "=r"(r[2]), "=r"(r[3])
                 : "r"(addr));
}
__device__ __forceinline__ void mma16816(float* d, const uint32_t* a,
                                         uint32_t b0, uint32_t b1) {
    asm volatile(
        "mma.sync.aligned.m16n8k16.row.col.f32.bf16.bf16.f32 "
        "{%0,%1,%2,%3}, {%4,%5,%6,%7}, {%8,%9}, {%0,%1,%2,%3};"
        : "+f"(d[0]), "+f"(d[1]), "+f"(d[2]), "+f"(d[3])
        : "r"(a[0]), "r"(a[1]), "r"(a[2]), "r"(a[3]), "r"(b0), "r"(b1));
}
__device__ __forceinline__ void mma16816h(float* d, const uint32_t* a,
                                          uint32_t b0, uint32_t b1) {
    asm volatile(
        "mma.sync.aligned.m16n8k16.row.col.f32.f16.f16.f32 "
        "{%0,%1,%2,%3}, {%4,%5,%6,%7}, {%8,%9}, {%0,%1,%2,%3};"
        : "+f"(d[0]), "+f"(d[1]), "+f"(d[2]), "+f"(d[3])
        : "r"(a[0]), "r"(a[1]), "r"(a[2]), "r"(a[3]), "r"(b0), "r"(b1));
}

// ---- generic hi/lo bf16 mma over staged chunk (k_proj / k_out) ----
template <int PITCH, int NK16>
__device__ __forceinline__ void mma_chunk(
    const __nv_bfloat16* base, float acc[2][8][4],
    int wm, int wn, int at_r, int at_k, int bt_n, int bt_k) {
    const int ARR = 128 * PITCH;
    const __nv_bfloat16* Ah = base;
    const __nv_bfloat16* Al = Ah + ARR;
    const __nv_bfloat16* Bh = Ah + 2 * ARR;
    const __nv_bfloat16* Bl = Ah + 3 * ARR;
#pragma unroll
    for (int k16 = 0; k16 < NK16; k16++) {
        int kc = k16 * 16 + at_k;
        uint32_t ah[2][4], al[2][4];
#pragma unroll
        for (int mt = 0; mt < 2; mt++) {
            int row = wm * 32 + mt * 16 + at_r;
            ldsm4(ah[mt], cvsm(Ah + row * PITCH + kc));
            ldsm4(al[mt], cvsm(Al + row * PITCH + kc));
        }
        int kcb = k16 * 16 + bt_k;
#pragma unroll
        for (int np = 0; np < 4; np++) {
            int n = wn * 64 + np * 16 + bt_n;
            uint32_t bh[4], bl[4];
            ldsm4(bh, cvsm(Bh + n * PITCH + kcb));
            ldsm4(bl, cvsm(Bl + n * PITCH + kcb));
#pragma unroll
            for (int mt = 0; mt < 2; mt++) {
#pragma unroll
                for (int nt = 0; nt < 2; nt++) {
                    float* d = acc[mt][np * 2 + nt];
                    mma16816(d, ah[mt], bh[nt * 2], bh[nt * 2 + 1]);
                    mma16816(d, ah[mt], bl[nt * 2], bl[nt * 2 + 1]);
                    mma16816(d, al[mt], bh[nt * 2], bh[nt * 2 + 1]);
                }
            }
        }
    }
}

#define SPITCH 40
#define SARR   (128 * SPITCH)

// ---------------- kernel: cos/sin tables ------------------------------------
__global__ void k_cs(const float* __restrict__ pos) {
    int idx = blockIdx.x * 256 + threadIdx.x;
    if (idx >= NN * 3 * NFREQ) return;
    int c = idx & 63;
    int a = (idx >> 6) % 3;
    int n = idx / 192;
    float theta = (8.0f / (63.0f * 10.0f)) * (float)c;
    float ph = pos[n * 3 + a] * theta;
    float s, co;
    sincosf(ph, &s, &co);
    g_cos[idx] = co;
    g_sin[idx] = s;
}

// ---------------- kernel: q/k/v projections via bf16 hi/lo mma.sync -----------
__global__ void __launch_bounds__(256, 2)
k_proj(const float* __restrict__ X,
       const float* __restrict__ Wq, const float* __restrict__ bq,
       const float* __restrict__ Wk, const float* __restrict__ bk,
       const float* __restrict__ Wv, const float* __restrict__ bv) {
    extern __shared__ unsigned char smraw[];
    __nv_bfloat16* smb = (__nv_bfloat16*)smraw;

    int z = blockIdx.z;
    int p = z / 3, l = z % 3;
    const int cnt = (l == 0) ? 1 : (l == 1 ? 3 : 5);
    const int m0  = (l == 0) ? 0 : (l == 1 ? 1 : 4);
    int ntiles = (NN * cnt) >> 7;
    if ((int)blockIdx.x >= ntiles) return;

    const float* W    = (p == 0 ? Wq : (p == 1 ? Wk : Wv)) + l * FF * FF;
    const float* bias = (p == 0 ? bq : (p == 1 ? bk : bv));
    float* dst = (p == 0 ? g_q : (p == 1 ? g_k : g_v));

    int row0 = blockIdx.x * 128;
    int tid = threadIdx.x;
    int wid = tid >> 5, lane = tid & 31;
    int wm = wid & 3, wn = wid >> 2;
    int kq = tid & 7, rr = tid >> 3;
    int kk = tid & 31, ng = tid >> 5;

    const float* arow[4];
#pragma unroll
    for (int i = 0; i < 4; i++) {
        int rg = row0 + rr + i * 32;
        int node = rg / cnt, mi = rg - node * cnt;
        arow[i] = X + ((size_t)node * ND + (m0 + mi)) * FF;
    }

    float acc[2][8][4];
#pragma unroll
    for (int mt = 0; mt < 2; mt++)
#pragma unroll
        for (int nt = 0; nt < 8; nt++)
#pragma unroll
            for (int e = 0; e < 4; e++) acc[mt][nt][e] = 0.0f;

    int at_r = (lane & 7) + ((lane >> 3) & 1) * 8;
    int at_k = (lane >> 4) * 8;
    int bt_n = (lane & 7) + ((lane & 16) ? 8 : 0);
    int bt_k = ((lane >> 3) & 1) * 8;

    auto stage = [&](int c, int st) {
        int f0 = c * 32;
        __nv_bfloat16* Ahd = smb + (st * 4 + 0) * SARR;
        __nv_bfloat16* Ald = Ahd + SARR;
#pragma unroll
        for (int i = 0; i < 4; i++) {
            int r = rr + i * 32;
            float4 v = *(const float4*)(arow[i] + f0 + kq * 4);
            __nv_bfloat162 h01, l01, h23, l23;
            split2(v.x, v.y, h01, l01);
            split2(v.z, v.w, h23, l23);
            __nv_bfloat162* ph = (__nv_bfloat162*)(Ahd + r * SPITCH + kq * 4);
            ph[0] = h01; ph[1] = h23;
            __nv_bfloat162* pl = (__nv_bfloat162*)(Ald + r * SPITCH + kq * 4);
            pl[0] = l01; pl[1] = l23;
        }
        __nv_bfloat16* Bhd = smb + (st * 4 + 2) * SARR;
        __nv_bfloat16* Bld = Bhd + SARR;
#pragma unroll
        for (int j = 0; j < 4; j++) {
            int n0 = ng * 16 + j * 4;
            float4 w = *(const float4*)(W + (size_t)(f0 + kk) * 128 + n0);
            float ws[4] = {w.x, w.y, w.z, w.w};
#pragma unroll
            for (int e = 0; e < 4; e++) {
                __nv_bfloat16 h = __float2bfloat16_rn(ws[e]);
                __nv_bfloat16 lo = __float2bfloat16_rn(ws[e] - __bfloat162float(h));
                Bhd[(n0 + e) * SPITCH + kk] = h;
                Bld[(n0 + e) * SPITCH + kk] = lo;
            }
        }
    };

    stage(0, 0);
    __syncthreads();
    for (int c = 0; c < 4; c++) {
        int st = c & 1;
        if (c + 1 < 4) stage(c + 1, st ^ 1);
        mma_chunk<SPITCH, 2>(smb + st * 4 * SARR, acc, wm, wn, at_r, at_k, bt_n, bt_k);
        __syncthreads();
    }

    int tr = lane >> 2, tc = (lane & 3) * 2;
#pragma unroll
    for (int mt = 0; mt < 2; mt++) {
#pragma unroll
        for (int half = 0; half < 2; half++) {
            int rgl = row0 + wm * 32 + mt * 16 + tr + half * 8;
            int node = rgl / cnt, mi = rgl - node * cnt;
            size_t obase = (size_t)node * MCH + (m0 + mi) * FF;
#pragma unroll
            for (int nt = 0; nt < 8; nt++) {
                int col = wn * 64 + nt * 8 + tc;
                float d0 = acc[mt][nt][half * 2 + 0];
                float d1 = acc[mt][nt][half * 2 + 1];
                if (l == 0) { d0 += bias[col]; d1 += bias[col + 1]; }
                *(float2*)(dst + obase + col) = make_float2(d0, d1);
            }
        }
    }
}

// ---------------- kernel: score partials via fp16 single mma.sync -------------
// grid: x=ti(2), y=tj(2), z = b*9 + (a*3+mc). 12 double-buffered stages of K=64
// (32 channels x {cos,sin}); fp16 operands (err ~2^-12/elem -> S rel ~1e-4).
#define KP2 72
#define KA2 (128 * KP2)
#define KS_SMEM (2 * 2 * KA2 * 2)   // 2 stages x (A+B) x fp16 = 73728 B

__global__ void __launch_bounds__(256, 2)
k_score() {
    extern __shared__ unsigned char smraw[];
    __half* smh = (__half*)smraw;

    int zz = blockIdx.z;
    int b = zz / 9, sp = zz - b * 9;
    int a = sp / 3, mc = sp - a * 3;
    int nb_i = b * NB + blockIdx.x * 128;
    int nb_j = b * NB + blockIdx.y * 128;
    int tid = threadIdx.x;
    int wid = tid >> 5, lane = tid & 31;
    int wm = wid & 3, wn = wid >> 2;
    int kq = tid & 7, rr = tid >> 3;
    int chbase = mc * 384;

    float acc[2][8][4];
#pragma unroll
    for (int mt = 0; mt < 2; mt++)
#pragma unroll
        for (int nt = 0; nt < 8; nt++)
#pragma unroll
            for (int e = 0; e < 4; e++) acc[mt][nt][e] = 0.0f;

    int at_r = (lane & 7) + ((lane >> 3) & 1) * 8;
    int at_k = (lane >> 4) * 8;
    int bt_n = (lane & 7) + ((lane & 16) ? 8 : 0);
    int bt_k = ((lane >> 3) & 1) * 8;

    auto stage = [&](int c, int st) {
        int chl = c * 32 + kq * 4;
        int ch  = chbase + chl;
        int f   = (chl & 127) >> 1;
#pragma unroll
        for (int pass = 0; pass < 2; pass++) {
            const float* src = pass == 0 ? g_q : g_k;
            int nb = pass == 0 ? nb_i : nb_j;
            __half* D = smh + st * 2 * KA2 + pass * KA2;
#pragma unroll
            for (int i = 0; i < 4; i++) {
                int r = rr + i * 32;
                int node = nb + r;
                const float* tc = g_cos + node * 192 + a * 64 + f;
                const float* ts = g_sin + node * 192 + a * 64 + f;
                float c0 = tc[0], c1 = tc[1];
                float s0 = ts[0], s1 = ts[1];
                float4 v = *(const float4*)(src + (size_t)node * MCH + ch);
                union { __half2 h2[2]; uint2 u; } p;
                p.h2[0] = __floats2half2_rn(v.x * c0, v.y * c0);
                p.h2[1] = __floats2half2_rn(v.z * c1, v.w * c1);
                *(uint2*)(D + r * KP2 + kq * 4) = p.u;
                p.h2[0] = __floats2half2_rn(v.x * s0, v.y * s0);
                p.h2[1] = __floats2half2_rn(v.z * s1, v.w * s1);
                *(uint2*)(D + r * KP2 + 32 + kq * 4) = p.u;
            }
        }
    };

    auto mma_f16 = [&](int st) {
        const __half* A = smh + st * 2 * KA2;
        const __half* B = A + KA2;
#pragma unroll
        for (int k16 = 0; k16 < 4; k16++) {
            int kc = k16 * 16 + at_k;
            uint32_t ah[2][4];
#pragma unroll
            for (int mt = 0; mt < 2; mt++) {
                int row = wm * 32 + mt * 16 + at_r;
                ldsm4(ah[mt], cvsm(A + row * KP2 + kc));
            }
            int kcb = k16 * 16 + bt_k;
#pragma unroll
            for (int np = 0; np < 4; np++) {
                int n = wn * 64 + np * 16 + bt_n;
                uint32_t bb[4];
                ldsm4(bb, cvsm(B + n * KP2 + kcb));
#pragma unroll
                for (int mt = 0; mt < 2; mt++) {
#pragma unroll
                    for (int nt = 0; nt < 2; nt++) {
                        mma16816h(acc[mt][np * 2 + nt], ah[mt],
                                  bb[nt * 2], bb[nt * 2 + 1]);
                    }
                }
            }
        }
    };

    stage(0, 0);
    __syncthreads();
    for (int c = 0; c < 12; c++) {
        int st = c & 1;
        if (c + 1 < 12) stage(c + 1, st ^ 1);
        mma_f16(st);
        __syncthreads();
    }

    size_t base = ((size_t)sp * BB + b) * (NB * NB);
    int gr = blockIdx.x * 128 + wm * 32;
    int gc = blockIdx.y * 128 + wn * 64;
    int tr = lane >> 2, tc2 = (lane & 3) * 2;
#pragma unroll
    for (int mt = 0; mt < 2; mt++) {
#pragma unroll
        for (int nt = 0; nt < 8; nt++) {
            int r0 = gr + mt * 16 + tr;
            int cc = gc + nt * 8 + tc2;
            float2 d01 = make_float2(acc[mt][nt][0], acc[mt][nt][1]);
            float2 d23 = make_float2(acc[mt][nt][2], acc[mt][nt][3]);
            *(float2*)(g_Spart + base + (size_t)r0 * NB + cc) = d01;
            *(float2*)(g_Spart + base + (size_t)(r0 + 8) * NB + cc) = d23;
        }
    }
}

// ---------------- kernel: slab reduce -----------------------------------------
__global__ void k_reduceS() {
    int i = blockIdx.x * 256 + threadIdx.x;
    if (i >= SZSLAB) return;
    float s = 0.0f;
#pragma unroll
    for (int sl = 0; sl < 9; sl++) s += g_Spart[(size_t)sl * SZSLAB + i];
    g_S[i] = s * (1.0f / 3.0f);   // = 2 * grid_w (pairing factor * 1/6)
}

// ---------------- kernel: out = Sbar @ V (+mask) via bf16 hi/lo mma ------------
__global__ void __launch_bounds__(256, 2)
k_out(const int* __restrict__ bseg, const int* __restrict__ gmask,
      float* __restrict__ out) {
    extern __shared__ unsigned char smraw[];
    __nv_bfloat16* smb = (__nv_bfloat16*)smraw;

    int b = blockIdx.z;
    int r0 = blockIdx.x * 128;
    int d0 = blockIdx.y * 128;
    int tid = threadIdx.x;
    int wid = tid >> 5, lane = tid & 31;
    int wm = wid & 3, wn = wid >> 2;
    int kq = tid & 7, rr = tid >> 3;
    int kk = tid & 31, ng = tid >> 5;

    float acc[2][8][4];
#pragma unroll
    for (int mt = 0; mt < 2; mt++)
#pragma unroll
        for (int nt = 0; nt < 8; nt++)
#pragma unroll
            for (int e = 0; e < 4; e++) acc[mt][nt][e] = 0.0f;

    int at_r = (lane & 7) + ((lane >> 3) & 1) * 8;
    int at_k = (lane >> 4) * 8;
    int bt_n = (lane & 7) + ((lane & 16) ? 8 : 0);
    int bt_k = ((lane >> 3) & 1) * 8;

    auto stage = [&](int c, int st) {
        int j0 = c * 32;
        __nv_bfloat16* Ahd = smb + (st * 4 + 0) * SARR;
        __nv_bfloat16* Ald = Ahd + SARR;
#pragma unroll
        for (int i = 0; i < 4; i++) {
            int r = rr + i * 32;
            float4 v = *(const float4*)(g_S + ((size_t)b * NB + r0 + r) * NB + j0 + kq * 4);
            __nv_bfloat162 h01, l01, h23, l23;
            split2(v.x, v.y, h01, l01);
            split2(v.z, v.w, h23, l23);
            __nv_bfloat162* ph = (__nv_bfloat162*)(Ahd + r * SPITCH + kq * 4);
            ph[0] = h01; ph[1] = h23;
            __nv_bfloat162* pl = (__nv_bfloat162*)(Ald + r * SPITCH + kq * 4);
            pl[0] = l01; pl[1] = l23;
        }
        __nv_bfloat16* Bhd = smb + (st * 4 + 2) * SARR;
        __nv_bfloat16* Bld = Bhd + SARR;
#pragma unroll
        for (int j = 0; j < 4; j++) {
            int n0 = ng * 16 + j * 4;
            float4 v = *(const float4*)(g_v + ((size_t)(b * NB + j0 + kk)) * MCH + d0 + n0);
            float vs[4] = {v.x, v.y, v.z, v.w};
#pragma unroll
            for (int e = 0; e < 4; e++) {
                __nv_bfloat16 h = __float2bfloat16_rn(vs[e]);
                __nv_bfloat16 lo = __float2bfloat16_rn(vs[e] - __bfloat162float(h));
                Bhd[(n0 + e) * SPITCH + kk] = h;
                Bld[(n0 + e) * SPITCH + kk] = lo;
            }
        }
    };

    stage(0, 0);
    __syncthreads();
    for (int c = 0; c < 8; c++) {
        int st = c & 1;
        if (c + 1 < 8) stage(c + 1, st ^ 1);
        mma_chunk<SPITCH, 2>(smb + st * 4 * SARR, acc, wm, wn, at_r, at_k, bt_n, bt_k);
        __syncthreads();
    }

    int tr = lane >> 2, tc = (lane & 3) * 2;
#pragma unroll
    for (int mt = 0; mt < 2; mt++) {
#pragma unroll
        for (int half = 0; half < 2; half++) {
            int node = b * NB + r0 + wm * 32 + mt * 16 + tr + half * 8;
            bool mk = gmask[bseg[node]] != 0;
#pragma unroll
            for (int nt = 0; nt < 8; nt++) {
                int col = wn * 64 + nt * 8 + tc;
                float o0 = mk ? acc[mt][nt][half * 2 + 0] : 0.0f;
                float o1 = mk ? acc[mt][nt][half * 2 + 1] : 0.0f;
                *(float2*)(out + (size_t)node * MCH + d0 + col) = make_float2(o0, o1);
            }
        }
    }
}

// ---------------- launcher ----------------------------------------------------
extern "C" void kernel_launch(void* const* d_in, const int* in_sizes, int n_in,
                              void* d_out, int out_size) {
    const float* X   = (const float*)d_in[0];
    const float* pos = (const float*)d_in[1];
    const int* bseg  = (const int*)d_in[2];
    const int* gmask = (const int*)d_in[3];   // bool -> int32 in harness
    const float* Wq = (const float*)d_in[4];
    const float* bq = (const float*)d_in[5];
    const float* Wk = (const float*)d_in[6];
    const float* bk = (const float*)d_in[7];
    const float* Wv = (const float*)d_in[8];
    const float* bv = (const float*)d_in[9];
    float* out = (float*)d_out;

    cudaFuncSetAttribute(k_proj,  cudaFuncAttributeMaxDynamicSharedMemorySize, 81920);
    cudaFuncSetAttribute(k_score, cudaFuncAttributeMaxDynamicSharedMemorySize, KS_SMEM);
    cudaFuncSetAttribute(k_out,   cudaFuncAttributeMaxDynamicSharedMemorySize, 81920);

    k_cs<<<(NN * 3 * NFREQ + 255) / 256, 256>>>(pos);
    k_proj<<<dim3(160, 1, 9), 256, 81920>>>(X, Wq, bq, Wk, bk, Wv, bv);
    k_score<<<dim3(2, 2, BB * 9), 256, KS_SMEM>>>();
    k_reduceS<<<(SZSLAB + 255) / 256, 256>>>();
    k_out<<<dim3(2, 9, BB), 256, 81920>>>(bseg, gmask, out);
}

// round 9
// speedup vs baseline: 3.3343x; 1.1631x over previous
#include <cuda_runtime.h>
#include <cuda_fp16.h>
#include <cstdint>

#define NN   4096
#define BB   16
#define NB   256      // nodes per batch
#define ND   9        // NUM_DEG
#define FF   128
#define MCH  1152     // 9*128
#define NFREQ 64
#define SZSLAB (BB * NB * NB)

// ---------------- scratch (static device memory; no allocations) ------------
__device__ float g_q[NN * MCH];
__device__ float g_k[NN * MCH];
__device__ float g_v[NN * MCH];
__device__ float g_cos[NN * 3 * NFREQ];
__device__ float g_sin[NN * 3 * NFREQ];
__device__ float g_Spart[9u * SZSLAB];   // 9 partial slabs
__device__ float g_S[SZSLAB];

// ---------------- helpers ------------------------------------------------------
__device__ __forceinline__ uint32_t cvsm(const void* p) {
    return (uint32_t)__cvta_generic_to_shared(p);
}
__device__ __forceinline__ void ldsm4(uint32_t* r, uint32_t addr) {
    asm volatile("ldmatrix.sync.aligned.m8n8.x4.shared.b16 {%0,%1,%2,%3}, [%4];"
                 : "=r"(r[0]), "=r"(r[1]), "=r"(r[2]), "=r"(r[3])
                 : "r"(addr));
}
__device__ __forceinline__ void mma16816h(float* d, const uint32_t* a,
                                          uint32_t b0, uint32_t b1) {
    asm volatile(
        "mma.sync.aligned.m16n8k16.row.col.f32.f16.f16.f32 "
        "{%0,%1,%2,%3}, {%4,%5,%6,%7}, {%8,%9}, {%0,%1,%2,%3};"
        : "+f"(d[0]), "+f"(d[1]), "+f"(d[2]), "+f"(d[3])
        : "r"(a[0]), "r"(a[1]), "r"(a[2]), "r"(a[3]), "r"(b0), "r"(b1));
}

// ---- fp16 single-term mma over staged chunk: A at base, B at base+ARR ----
template <int PITCH, int NK16>
__device__ __forceinline__ void mma_chunk_h(
    const __half* base, float acc[2][8][4],
    int wm, int wn, int at_r, int at_k, int bt_n, int bt_k) {
    const int ARR = 128 * PITCH;
    const __half* A = base;
    const __half* B = base + ARR;
#pragma unroll
    for (int k16 = 0; k16 < NK16; k16++) {
        int kc = k16 * 16 + at_k;
        uint32_t ah[2][4];
#pragma unroll
        for (int mt = 0; mt < 2; mt++) {
            int row = wm * 32 + mt * 16 + at_r;
            ldsm4(ah[mt], cvsm(A + row * PITCH + kc));
        }
        int kcb = k16 * 16 + bt_k;
#pragma unroll
        for (int np = 0; np < 4; np++) {
            int n = wn * 64 + np * 16 + bt_n;
            uint32_t bb[4];
            ldsm4(bb, cvsm(B + n * PITCH + kcb));
#pragma unroll
            for (int mt = 0; mt < 2; mt++) {
#pragma unroll
                for (int nt = 0; nt < 2; nt++) {
                    mma16816h(acc[mt][np * 2 + nt], ah[mt],
                              bb[nt * 2], bb[nt * 2 + 1]);
                }
            }
        }
    }
}

#define SPITCH 40
#define SARR   (128 * SPITCH)
#define PO_SMEM (2 * 2 * SARR * 2)   // 2 stages x (A+B) x fp16 = 40960 B

// ---------------- kernel: cos/sin tables ------------------------------------
__global__ void k_cs(const float* __restrict__ pos) {
    int idx = blockIdx.x * 256 + threadIdx.x;
    if (idx >= NN * 3 * NFREQ) return;
    int c = idx & 63;
    int a = (idx >> 6) % 3;
    int n = idx / 192;
    float theta = (8.0f / (63.0f * 10.0f)) * (float)c;
    float ph = pos[n * 3 + a] * theta;
    float s, co;
    sincosf(ph, &s, &co);
    g_cos[idx] = co;
    g_sin[idx] = s;
}

// ---------------- kernel: q/k/v projections via fp16 mma.sync ------------------
__global__ void __launch_bounds__(256, 2)
k_proj(const float* __restrict__ X,
       const float* __restrict__ Wq, const float* __restrict__ bq,
       const float* __restrict__ Wk, const float* __restrict__ bk,
       const float* __restrict__ Wv, const float* __restrict__ bv) {
    extern __shared__ unsigned char smraw[];
    __half* smh = (__half*)smraw;

    int z = blockIdx.z;
    int p = z / 3, l = z % 3;
    const int cnt = (l == 0) ? 1 : (l == 1 ? 3 : 5);
    const int m0  = (l == 0) ? 0 : (l == 1 ? 1 : 4);
    int ntiles = (NN * cnt) >> 7;
    if ((int)blockIdx.x >= ntiles) return;

    const float* W    = (p == 0 ? Wq : (p == 1 ? Wk : Wv)) + l * FF * FF;
    const float* bias = (p == 0 ? bq : (p == 1 ? bk : bv));
    float* dst = (p == 0 ? g_q : (p == 1 ? g_k : g_v));

    int row0 = blockIdx.x * 128;
    int tid = threadIdx.x;
    int wid = tid >> 5, lane = tid & 31;
    int wm = wid & 3, wn = wid >> 2;
    int kq = tid & 7, rr = tid >> 3;
    int kk = tid & 31, ng = tid >> 5;

    const float* arow[4];
#pragma unroll
    for (int i = 0; i < 4; i++) {
        int rg = row0 + rr + i * 32;
        int node = rg / cnt, mi = rg - node * cnt;
        arow[i] = X + ((size_t)node * ND + (m0 + mi)) * FF;
    }

    float acc[2][8][4];
#pragma unroll
    for (int mt = 0; mt < 2; mt++)
#pragma unroll
        for (int nt = 0; nt < 8; nt++)
#pragma unroll
            for (int e = 0; e < 4; e++) acc[mt][nt][e] = 0.0f;

    int at_r = (lane & 7) + ((lane >> 3) & 1) * 8;
    int at_k = (lane >> 4) * 8;
    int bt_n = (lane & 7) + ((lane & 16) ? 8 : 0);
    int bt_k = ((lane >> 3) & 1) * 8;

    auto stage = [&](int c, int st) {
        int f0 = c * 32;
        __half* Ah = smh + st * 2 * SARR;
#pragma unroll
        for (int i = 0; i < 4; i++) {
            int r = rr + i * 32;
            float4 v = *(const float4*)(arow[i] + f0 + kq * 4);
            union { __half2 h2[2]; uint2 u; } pk;
            pk.h2[0] = __floats2half2_rn(v.x, v.y);
            pk.h2[1] = __floats2half2_rn(v.z, v.w);
            *(uint2*)(Ah + r * SPITCH + kq * 4) = pk.u;
        }
        __half* Bh = Ah + SARR;
#pragma unroll
        for (int j = 0; j < 4; j++) {
            int n0 = ng * 16 + j * 4;
            float4 w = *(const float4*)(W + (size_t)(f0 + kk) * 128 + n0);
            float ws[4] = {w.x, w.y, w.z, w.w};
#pragma unroll
            for (int e = 0; e < 4; e++)
                Bh[(n0 + e) * SPITCH + kk] = __float2half_rn(ws[e]);
        }
    };

    stage(0, 0);
    __syncthreads();
    for (int c = 0; c < 4; c++) {
        int st = c & 1;
        if (c + 1 < 4) stage(c + 1, st ^ 1);
        mma_chunk_h<SPITCH, 2>(smh + st * 2 * SARR, acc, wm, wn, at_r, at_k, bt_n, bt_k);
        __syncthreads();
    }

    int tr = lane >> 2, tc = (lane & 3) * 2;
#pragma unroll
    for (int mt = 0; mt < 2; mt++) {
#pragma unroll
        for (int half = 0; half < 2; half++) {
            int rgl = row0 + wm * 32 + mt * 16 + tr + half * 8;
            int node = rgl / cnt, mi = rgl - node * cnt;
            size_t obase = (size_t)node * MCH + (m0 + mi) * FF;
#pragma unroll
            for (int nt = 0; nt < 8; nt++) {
                int col = wn * 64 + nt * 8 + tc;
                float d0 = acc[mt][nt][half * 2 + 0];
                float d1 = acc[mt][nt][half * 2 + 1];
                if (l == 0) { d0 += bias[col]; d1 += bias[col + 1]; }
                *(float2*)(dst + obase + col) = make_float2(d0, d1);
            }
        }
    }
}

// ---------------- kernel: score partials via fp16 mma.sync (unchanged R8) ----
#define KP2 72
#define KA2 (128 * KP2)
#define KS_SMEM (2 * 2 * KA2 * 2)   // 73728 B

__global__ void __launch_bounds__(256, 2)
k_score() {
    extern __shared__ unsigned char smraw[];
    __half* smh = (__half*)smraw;

    int zz = blockIdx.z;
    int b = zz / 9, sp = zz - b * 9;
    int a = sp / 3, mc = sp - a * 3;
    int nb_i = b * NB + blockIdx.x * 128;
    int nb_j = b * NB + blockIdx.y * 128;
    int tid = threadIdx.x;
    int wid = tid >> 5, lane = tid & 31;
    int wm = wid & 3, wn = wid >> 2;
    int kq = tid & 7, rr = tid >> 3;
    int chbase = mc * 384;

    float acc[2][8][4];
#pragma unroll
    for (int mt = 0; mt < 2; mt++)
#pragma unroll
        for (int nt = 0; nt < 8; nt++)
#pragma unroll
            for (int e = 0; e < 4; e++) acc[mt][nt][e] = 0.0f;

    int at_r = (lane & 7) + ((lane >> 3) & 1) * 8;
    int at_k = (lane >> 4) * 8;
    int bt_n = (lane & 7) + ((lane & 16) ? 8 : 0);
    int bt_k = ((lane >> 3) & 1) * 8;

    auto stage = [&](int c, int st) {
        int chl = c * 32 + kq * 4;
        int ch  = chbase + chl;
        int f   = (chl & 127) >> 1;
#pragma unroll
        for (int pass = 0; pass < 2; pass++) {
            const float* src = pass == 0 ? g_q : g_k;
            int nb = pass == 0 ? nb_i : nb_j;
            __half* D = smh + st * 2 * KA2 + pass * KA2;
#pragma unroll
            for (int i = 0; i < 4; i++) {
                int r = rr + i * 32;
                int node = nb + r;
                const float* tc = g_cos + node * 192 + a * 64 + f;
                const float* ts = g_sin + node * 192 + a * 64 + f;
                float c0 = tc[0], c1 = tc[1];
                float s0 = ts[0], s1 = ts[1];
                float4 v = *(const float4*)(src + (size_t)node * MCH + ch);
                union { __half2 h2[2]; uint2 u; } p;
                p.h2[0] = __floats2half2_rn(v.x * c0, v.y * c0);
                p.h2[1] = __floats2half2_rn(v.z * c1, v.w * c1);
                *(uint2*)(D + r * KP2 + kq * 4) = p.u;
                p.h2[0] = __floats2half2_rn(v.x * s0, v.y * s0);
                p.h2[1] = __floats2half2_rn(v.z * s1, v.w * s1);
                *(uint2*)(D + r * KP2 + 32 + kq * 4) = p.u;
            }
        }
    };

    auto mma_f16 = [&](int st) {
        mma_chunk_h<KP2, 4>(smh + st * 2 * KA2, acc, wm, wn, at_r, at_k, bt_n, bt_k);
    };

    stage(0, 0);
    __syncthreads();
    for (int c = 0; c < 12; c++) {
        int st = c & 1;
        if (c + 1 < 12) stage(c + 1, st ^ 1);
        mma_f16(st);
        __syncthreads();
    }

    size_t base = ((size_t)sp * BB + b) * (NB * NB);
    int gr = blockIdx.x * 128 + wm * 32;
    int gc = blockIdx.y * 128 + wn * 64;
    int tr = lane >> 2, tc2 = (lane & 3) * 2;
#pragma unroll
    for (int mt = 0; mt < 2; mt++) {
#pragma unroll
        for (int nt = 0; nt < 8; nt++) {
            int r0 = gr + mt * 16 + tr;
            int cc = gc + nt * 8 + tc2;
            float2 d01 = make_float2(acc[mt][nt][0], acc[mt][nt][1]);
            float2 d23 = make_float2(acc[mt][nt][2], acc[mt][nt][3]);
            *(float2*)(g_Spart + base + (size_t)r0 * NB + cc) = d01;
            *(float2*)(g_Spart + base + (size_t)(r0 + 8) * NB + cc) = d23;
        }
    }
}

// ---------------- kernel: slab reduce -----------------------------------------
__global__ void k_reduceS() {
    int i = blockIdx.x * 256 + threadIdx.x;
    if (i >= SZSLAB) return;
    float s = 0.0f;
#pragma unroll
    for (int sl = 0; sl < 9; sl++) s += g_Spart[(size_t)sl * SZSLAB + i];
    g_S[i] = s * (1.0f / 3.0f);   // = 2 * grid_w (pairing factor * 1/6)
}

// ---------------- kernel: out = Sbar @ V (+mask) via fp16 mma.sync -------------
__global__ void __launch_bounds__(256, 2)
k_out(const int* __restrict__ bseg, const int* __restrict__ gmask,
      float* __restrict__ out) {
    extern __shared__ unsigned char smraw[];
    __half* smh = (__half*)smraw;

    int b = blockIdx.z;
    int r0 = blockIdx.x * 128;
    int d0 = blockIdx.y * 128;
    int tid = threadIdx.x;
    int wid = tid >> 5, lane = tid & 31;
    int wm = wid & 3, wn = wid >> 2;
    int kq = tid & 7, rr = tid >> 3;
    int kk = tid & 31, ng = tid >> 5;

    float acc[2][8][4];
#pragma unroll
    for (int mt = 0; mt < 2; mt++)
#pragma unroll
        for (int nt = 0; nt < 8; nt++)
#pragma unroll
            for (int e = 0; e < 4; e++) acc[mt][nt][e] = 0.0f;

    int at_r = (lane & 7) + ((lane >> 3) & 1) * 8;
    int at_k = (lane >> 4) * 8;
    int bt_n = (lane & 7) + ((lane & 16) ? 8 : 0);
    int bt_k = ((lane >> 3) & 1) * 8;

    auto stage = [&](int c, int st) {
        int j0 = c * 32;
        __half* Ah = smh + st * 2 * SARR;
#pragma unroll
        for (int i = 0; i < 4; i++) {
            int r = rr + i * 32;
            float4 v = *(const float4*)(g_S + ((size_t)b * NB + r0 + r) * NB + j0 + kq * 4);
            union { __half2 h2[2]; uint2 u; } pk;
            pk.h2[0] = __floats2half2_rn(v.x, v.y);
            pk.h2[1] = __floats2half2_rn(v.z, v.w);
            *(uint2*)(Ah + r * SPITCH + kq * 4) = pk.u;
        }
        __half* Bh = Ah + SARR;
#pragma unroll
        for (int j = 0; j < 4; j++) {
            int n0 = ng * 16 + j * 4;
            float4 v = *(const float4*)(g_v + ((size_t)(b * NB + j0 + kk)) * MCH + d0 + n0);
            float vs[4] = {v.x, v.y, v.z, v.w};
#pragma unroll
            for (int e = 0; e < 4; e++)
                Bh[(n0 + e) * SPITCH + kk] = __float2half_rn(vs[e]);
        }
    };

    stage(0, 0);
    __syncthreads();
    for (int c = 0; c < 8; c++) {
        int st = c & 1;
        if (c + 1 < 8) stage(c + 1, st ^ 1);
        mma_chunk_h<SPITCH, 2>(smh + st * 2 * SARR, acc, wm, wn, at_r, at_k, bt_n, bt_k);
        __syncthreads();
    }

    int tr = lane >> 2, tc = (lane & 3) * 2;
#pragma unroll
    for (int mt = 0; mt < 2; mt++) {
#pragma unroll
        for (int half = 0; half < 2; half++) {
            int node = b * NB + r0 + wm * 32 + mt * 16 + tr + half * 8;
            bool mk = gmask[bseg[node]] != 0;
#pragma unroll
            for (int nt = 0; nt < 8; nt++) {
                int col = wn * 64 + nt * 8 + tc;
                float o0 = mk ? acc[mt][nt][half * 2 + 0] : 0.0f;
                float o1 = mk ? acc[mt][nt][half * 2 + 1] : 0.0f;
                *(float2*)(out + (size_t)node * MCH + d0 + col) = make_float2(o0, o1);
            }
        }
    }
}

// ---------------- launcher ----------------------------------------------------
extern "C" void kernel_launch(void* const* d_in, const int* in_sizes, int n_in,
                              void* d_out, int out_size) {
    const float* X   = (const float*)d_in[0];
    const float* pos = (const float*)d_in[1];
    const int* bseg  = (const int*)d_in[2];
    const int* gmask = (const int*)d_in[3];   // bool -> int32 in harness
    const float* Wq = (const float*)d_in[4];
    const float* bq = (const float*)d_in[5];
    const float* Wk = (const float*)d_in[6];
    const float* bk = (const float*)d_in[7];
    const float* Wv = (const float*)d_in[8];
    const float* bv = (const float*)d_in[9];
    float* out = (float*)d_out;

    cudaFuncSetAttribute(k_proj,  cudaFuncAttributeMaxDynamicSharedMemorySize, PO_SMEM);
    cudaFuncSetAttribute(k_score, cudaFuncAttributeMaxDynamicSharedMemorySize, KS_SMEM);
    cudaFuncSetAttribute(k_out,   cudaFuncAttributeMaxDynamicSharedMemorySize, PO_SMEM);

    k_cs<<<(NN * 3 * NFREQ + 255) / 256, 256>>>(pos);
    k_proj<<<dim3(160, 1, 9), 256, PO_SMEM>>>(X, Wq, bq, Wk, bk, Wv, bv);
    k_score<<<dim3(2, 2, BB * 9), 256, KS_SMEM>>>();
    k_reduceS<<<(SZSLAB + 255) / 256, 256>>>();
    k_out<<<dim3(2, 9, BB), 256, PO_SMEM>>>(bseg, gmask, out);
}